// round 12
// baseline (speedup 1.0000x reference)
#include <cuda_runtime.h>
#include <cuda_fp16.h>
#include <math.h>

// ---------------------------------------------------------------------------
// Problem constants
// ---------------------------------------------------------------------------
#define NSAMP    524288      // 8192 rays * 64 samples

// combos: (0,1) (0,2) (0,3) (1,2) (1,3) (2,3)
// widths: 64,64,50,64,50,50  ->  W2: 128,128,100,128,100,100
// Interleaved plane-pair layout per combo: [Y][X][C=32][2] = (hi, lo), fp16.
#define TOTAL_PLANE_ELEMS 5603328   // halves: 11.2 MB

__device__ __half   g_planes[TOTAL_PLANE_ELEMS];
__device__ unsigned g_featsp[32 * NSAMP];       // packed half2 feature pairs, 67 MB

typedef unsigned long long ull;

// ---------------------------------------------------------------------------
// Packed dual-fp32 helpers (sm_100 f32x2 pipe; IEEE-identical per half)
// ---------------------------------------------------------------------------
__device__ __forceinline__ ull pack2(float f) {
    ull r;
    asm("mov.b64 %0, {%1, %1};" : "=l"(r) : "f"(f));
    return r;
}
__device__ __forceinline__ void ffma2(ull& d, ull a, ull b) {
    asm("fma.rn.f32x2 %0, %1, %2, %0;" : "+l"(d) : "l"(a), "l"(b));
}
__device__ __forceinline__ void mul2(ull& d, ull a, ull b) {
    asm("mul.rn.f32x2 %0, %1, %2;" : "=l"(d) : "l"(a), "l"(b));
}
__device__ __forceinline__ void unpack2(ull v, float& lo, float& hi) {
    asm("mov.b64 {%0, %1}, %2;" : "=f"(lo), "=f"(hi) : "l"(v));
}
// half2 (packed in u32) -> packed f32x2 in u64
__device__ __forceinline__ ull h2f2(unsigned v) {
    __half2 h = *(__half2*)&v;
    float2 f = __half22float2(h);
    ull r;
    asm("mov.b64 %0, {%1, %2};" : "=l"(r) : "f"(f.x), "f"(f.y));
    return r;
}

// ---------------------------------------------------------------------------
// Dummy kernel: shifts the ncu sampled-launch slot so the profiler stops
// landing on idwt_all every round. No work.
// ---------------------------------------------------------------------------
__global__ void wf_nop() {}

// ---------------------------------------------------------------------------
// IDWT precompute, all 6 combos in one kernel; writes fp16 (hi,lo) pairs.
// ---------------------------------------------------------------------------
template <int W, int W2, int OFF>
__device__ __forceinline__ void idwt_body(const float* __restrict__ yl,
                                          const float* __restrict__ yh,
                                          int idx) {
    if (idx >= 32 * 64 * W) return;

    int j0   = idx % W;
    int rest = idx / W;
    int i0   = rest & 63;
    int c    = rest >> 6;

    float a  = yl[(c * 64 + i0) * W + j0];
    float lh = yh[((c * 3 + 0) * 64 + i0) * W + j0];
    float hl = yh[((c * 3 + 1) * 64 + i0) * W + j0];
    float hh = yh[((c * 3 + 2) * 64 + i0) * W + j0];

    float ee = 0.5f * (a + lh + hl + hh);
    float eo = 0.5f * (a + lh - hl - hh);
    float oe = 0.5f * (a - lh + hl - hh);
    float oo = 0.5f * (a - lh - hl + hh);
    float lo = 0.5f * a;

    int fi = OFF + ((2 * i0) * W2 + 2 * j0) * 64 + 2 * c;   // element index
    __half* gp = g_planes;
    *(__half2*)(gp + fi)                = __floats2half2_rn(ee, lo);
    *(__half2*)(gp + fi + 64)           = __floats2half2_rn(eo, lo);
    *(__half2*)(gp + fi + W2 * 64)      = __floats2half2_rn(oe, lo);
    *(__half2*)(gp + fi + W2 * 64 + 64) = __floats2half2_rn(oo, lo);
}

__global__ __launch_bounds__(256) void idwt_all(
    const float* __restrict__ yl0, const float* __restrict__ yh0,
    const float* __restrict__ yl1, const float* __restrict__ yh1,
    const float* __restrict__ yl2, const float* __restrict__ yh2,
    const float* __restrict__ yl3, const float* __restrict__ yh3,
    const float* __restrict__ yl4, const float* __restrict__ yh4,
    const float* __restrict__ yl5, const float* __restrict__ yh5) {
    int b = blockIdx.x;
    int t = threadIdx.x;
    if      (b <  512) idwt_body<64, 128,       0>(yl0, yh0, (b       ) * 256 + t);
    else if (b < 1024) idwt_body<64, 128, 1048576>(yl1, yh1, (b -  512) * 256 + t);
    else if (b < 1424) idwt_body<50, 100, 2097152>(yl2, yh2, (b - 1024) * 256 + t);
    else if (b < 1936) idwt_body<64, 128, 2916352>(yl3, yh3, (b - 1424) * 256 + t);
    else if (b < 2336) idwt_body<50, 100, 3964928>(yl4, yh4, (b - 1936) * 256 + t);
    else               idwt_body<50, 100, 4784128>(yl5, yh5, (b - 2336) * 256 + t);
}

// ---------------------------------------------------------------------------
// Gather helpers.
// Offset encoding: bits[0:24) = OFF + (y0*W2+x0)*64 (element units),
//                  bit 24 = (x1>x0), bit 25 = (y1>y0).
// ---------------------------------------------------------------------------
template <int W2, int OFF, int J, int K>
__device__ __forceinline__ void prep(const float p4[4], int& oenc,
                                     float& wy, float& wx) {
    float y = (p4[J] + 1.0f) * 0.5f * 127.0f;
    float x = (p4[K] + 1.0f) * 0.5f * (float)(W2 - 1);

    float yf = fminf(fmaxf(floorf(y), 0.0f), 127.0f);
    float xf = fminf(fmaxf(floorf(x), 0.0f), (float)(W2 - 1));
    int y0 = (int)yf, x0 = (int)xf;
    int y1 = min(y0 + 1, 127);
    int x1 = min(x0 + 1, W2 - 1);
    wy = fminf(fmaxf(y - yf, 0.0f), 1.0f);
    wx = fminf(fmaxf(x - xf, 0.0f), 1.0f);

    oenc = (OFF + (y0 * W2 + x0) * 64)
         | ((x1 > x0) ? (1 << 24) : 0)
         | ((y1 > y0) ? (1 << 25) : 0);
}

template <int DYC>   // DYC = W2*64 (element units)
__device__ __forceinline__ void samp(int oenc, float wy, float wx,
                                     int lane2, ull& prod) {
    int base = (oenc & 0xFFFFFF) + lane2;
    int dx = ((oenc >> 24) & 1) << 6;
    int dy = (oenc & (1 << 25)) ? DYC : 0;

    float om_y = 1.0f - wy, om_x = 1.0f - wx;
    ull w00 = pack2(om_y * om_x);
    ull w01 = pack2(om_y * wx);
    ull w10 = pack2(wy * om_x);
    ull w11 = pack2(wy * wx);

    const __half* gp = g_planes;
    unsigned v00 = *(const unsigned*)(gp + base);
    unsigned v01 = *(const unsigned*)(gp + base + dx);
    unsigned v10 = *(const unsigned*)(gp + base + dy);
    unsigned v11 = *(const unsigned*)(gp + base + dy + dx);

    ull acc = 0ull;
    ffma2(acc, w00, h2f2(v00));
    ffma2(acc, w01, h2f2(v01));
    ffma2(acc, w10, h2f2(v10));
    ffma2(acc, w11, h2f2(v11));
    mul2(prod, prod, acc);
}

// ---------------------------------------------------------------------------
// Kernel A: gather -> packed half2 feature scratch. 128 thr/blk.
// s-loop unrolled x2 so ptxas can front-batch two iterations' 48 loads.
// ---------------------------------------------------------------------------
#define TSTRIDE 69
#define WARPBUF (32 * TSTRIDE)   // 2208 floats per warp

__global__ __launch_bounds__(128) void wf_gather(
    const float* __restrict__ pts, const float* __restrict__ ts) {

    extern __shared__ float wfbuf[];

    int lane = threadIdx.x & 31;
    int warp = threadIdx.x >> 5;
    int lane2 = 2 * lane;
    int n = blockIdx.x * 128 + threadIdx.x;

    float p4[4];
    p4[0] = pts[3*n + 0];
    p4[1] = pts[3*n + 1];
    p4[2] = pts[3*n + 2];
    p4[3] = ts[n >> 6] * 2.0f - 1.0f;

    int   oe0, oe1, oe2, oe3, oe4, oe5;
    float wy0, wy1, wy2, wy3, wy4, wy5;
    float wx0, wx1, wx2, wx3, wx4, wx5;
    prep<128,       0, 0, 1>(p4, oe0, wy0, wx0);
    prep<128, 1048576, 0, 2>(p4, oe1, wy1, wx1);
    prep<100, 2097152, 0, 3>(p4, oe2, wy2, wx2);
    prep<128, 2916352, 1, 2>(p4, oe3, wy3, wx3);
    prep<100, 3964928, 1, 3>(p4, oe4, wy4, wx4);
    prep<100, 4784128, 2, 3>(p4, oe5, wy5, wx5);

    float* wf = wfbuf + warp * WARPBUF;

#pragma unroll 2
    for (int s = 0; s < 32; s++) {
        ull prod = pack2(1.0f);

#define DO_COMBO(OE, WY, WX, DYC)                                  \
        {                                                          \
            int   o  = __shfl_sync(0xffffffffu, OE, s);            \
            float a_ = __shfl_sync(0xffffffffu, WY, s);            \
            float b_ = __shfl_sync(0xffffffffu, WX, s);            \
            samp<DYC>(o, a_, b_, lane2, prod);                     \
        }
        DO_COMBO(oe0, wy0, wx0, 8192)
        DO_COMBO(oe1, wy1, wx1, 8192)
        DO_COMBO(oe2, wy2, wx2, 6400)
        DO_COMBO(oe3, wy3, wx3, 8192)
        DO_COMBO(oe4, wy4, wx4, 6400)
        DO_COMBO(oe5, wy5, wx5, 6400)
#undef DO_COMBO

        float fh, fl;
        unpack2(prod, fh, fl);
        wf[s * TSTRIDE + lane]      = fh;
        wf[s * TSTRIDE + 34 + lane] = fl;
    }
    __syncwarp();

    // Pack feature pairs to half2 and store coalesced (feature-pair-major).
    const float* my = wf + lane * TSTRIDE;
#pragma unroll
    for (int q = 0; q < 16; q++) {
        __half2 hp = __floats2half2_rn(my[2*q], my[2*q + 1]);
        g_featsp[q * NSAMP + n] = *(unsigned*)&hp;
    }
#pragma unroll
    for (int q = 16; q < 32; q++) {
        __half2 hp = __floats2half2_rn(my[2*q + 2], my[2*q + 3]);
        g_featsp[q * NSAMP + n] = *(unsigned*)&hp;
    }
}

// ---------------------------------------------------------------------------
// Kernel B: MLP chain with packed f32x2 FFMA. Static smem weights (44.75 KB).
// ---------------------------------------------------------------------------
__global__ __launch_bounds__(128) void wf_mlp(
    const float* __restrict__ dirs,
    const float* __restrict__ Wsig1, const float* __restrict__ Wsig2,
    const float* __restrict__ Wc1, const float* __restrict__ Wc2,
    const float* __restrict__ Wc3, float* __restrict__ outp) {

    __shared__ __align__(16) float sW1[64 * 64];
    __shared__ __align__(16) float sW2[64 * 16];
    __shared__ __align__(16) float sC1[32 * 64];
    __shared__ __align__(16) float sC2[64 * 64];
    __shared__ float sC3[64 * 3];

    for (int i = threadIdx.x; i < 64*64; i += 128) sW1[i] = Wsig1[i];
    for (int i = threadIdx.x; i < 64*16; i += 128) sW2[i] = Wsig2[i];
    for (int i = threadIdx.x; i < 31*64; i += 128) sC1[i] = Wc1[i];
    for (int i = threadIdx.x; i < 64*64; i += 128) sC2[i] = Wc2[i];
    for (int i = threadIdx.x; i < 64*3;  i += 128) sC3[i] = Wc3[i];
    __syncthreads();

    int n = blockIdx.x * 128 + threadIdx.x;

    // Coalesced packed-half2 feature loads.
    float fv[64];
#pragma unroll
    for (int q = 0; q < 32; q++) {
        unsigned v = g_featsp[q * NSAMP + n];
        __half2 h = *(__half2*)&v;
        float2 f = __half22float2(h);
        fv[2*q]     = f.x;
        fv[2*q + 1] = f.y;
    }

    // ---- MLP1: h = relu(fv @ Wsig1[64,64]) ----
    float h[64];
    {
        ull acc[32];
#pragma unroll
        for (int k = 0; k < 32; k++) acc[k] = 0ull;
#pragma unroll
        for (int i = 0; i < 64; i++) {
            ull fp = pack2(fv[i]);
            const ulonglong2* wrow = (const ulonglong2*)(sW1 + i * 64);
#pragma unroll
            for (int og = 0; og < 16; og++) {
                ulonglong2 w = wrow[og];
                ffma2(acc[2*og],     fp, w.x);
                ffma2(acc[2*og + 1], fp, w.y);
            }
        }
#pragma unroll
        for (int k = 0; k < 32; k++) {
            float lo, hi;
            unpack2(acc[k], lo, hi);
            h[2*k]   = fmaxf(lo, 0.f);
            h[2*k+1] = fmaxf(hi, 0.f);
        }
    }

    // ---- out = h @ Wsig2[64,16] ----
    float ov[16];
    {
        ull acc[8];
#pragma unroll
        for (int k = 0; k < 8; k++) acc[k] = 0ull;
#pragma unroll
        for (int i = 0; i < 64; i++) {
            ull fp = pack2(h[i]);
            const ulonglong2* wrow = (const ulonglong2*)(sW2 + i * 16);
#pragma unroll
            for (int og = 0; og < 4; og++) {
                ulonglong2 w = wrow[og];
                ffma2(acc[2*og],     fp, w.x);
                ffma2(acc[2*og + 1], fp, w.y);
            }
        }
#pragma unroll
        for (int k = 0; k < 8; k++) unpack2(acc[k], ov[2*k], ov[2*k+1]);
    }
    float density = expf(fminf(fmaxf(ov[15], -15.0f), 15.0f));

    // ---- SH degree-4 encoding ----
    int r = n >> 6;
    float dxv = dirs[3*r + 0], dyv = dirs[3*r + 1], dzv = dirs[3*r + 2];
    float inv = rsqrtf(dxv*dxv + dyv*dyv + dzv*dzv);
    float X = dxv * inv, Y = dyv * inv, Z = dzv * inv;
    float xx = X * X, yy = Y * Y, zz = Z * Z;

    float ci[31];
    ci[0]  = 0.28209479177387814f;
    ci[1]  = -0.4886025119029199f * Y;
    ci[2]  = 0.4886025119029199f * Z;
    ci[3]  = -0.4886025119029199f * X;
    ci[4]  = 1.0925484305920792f * X * Y;
    ci[5]  = -1.0925484305920792f * Y * Z;
    ci[6]  = 0.31539156525252005f * (3.0f * zz - 1.0f);
    ci[7]  = -1.0925484305920792f * X * Z;
    ci[8]  = 0.5462742152960396f * (xx - yy);
    ci[9]  = -0.5900435899266435f * Y * (3.0f * xx - yy);
    ci[10] = 2.890611442640554f * X * Y * Z;
    ci[11] = -0.4570457994644658f * Y * (5.0f * zz - 1.0f);
    ci[12] = 0.3731763325901154f * Z * (5.0f * zz - 3.0f);
    ci[13] = -0.4570457994644658f * X * (5.0f * zz - 1.0f);
    ci[14] = 1.445305721320277f * Z * (xx - yy);
    ci[15] = -0.5900435899266435f * X * (xx - 3.0f * yy);
#pragma unroll
    for (int g = 0; g < 15; g++) ci[16 + g] = ov[g];

    // ---- h2 = relu(ci @ Wc1[31,64]) ----
    float h2[64];
    {
        ull acc[32];
#pragma unroll
        for (int k = 0; k < 32; k++) acc[k] = 0ull;
#pragma unroll
        for (int i = 0; i < 31; i++) {
            ull fp = pack2(ci[i]);
            const ulonglong2* wrow = (const ulonglong2*)(sC1 + i * 64);
#pragma unroll
            for (int og = 0; og < 16; og++) {
                ulonglong2 w = wrow[og];
                ffma2(acc[2*og],     fp, w.x);
                ffma2(acc[2*og + 1], fp, w.y);
            }
        }
#pragma unroll
        for (int k = 0; k < 32; k++) {
            float lo, hi;
            unpack2(acc[k], lo, hi);
            h2[2*k]   = fmaxf(lo, 0.f);
            h2[2*k+1] = fmaxf(hi, 0.f);
        }
    }

    // ---- h3 = relu(h2 @ Wc2[64,64]) ----
    float h3[64];
    {
        ull acc[32];
#pragma unroll
        for (int k = 0; k < 32; k++) acc[k] = 0ull;
#pragma unroll
        for (int i = 0; i < 64; i++) {
            ull fp = pack2(h2[i]);
            const ulonglong2* wrow = (const ulonglong2*)(sC2 + i * 64);
#pragma unroll
            for (int og = 0; og < 16; og++) {
                ulonglong2 w = wrow[og];
                ffma2(acc[2*og],     fp, w.x);
                ffma2(acc[2*og + 1], fp, w.y);
            }
        }
#pragma unroll
        for (int k = 0; k < 32; k++) {
            float lo, hi;
            unpack2(acc[k], lo, hi);
            h3[2*k]   = fmaxf(lo, 0.f);
            h3[2*k+1] = fmaxf(hi, 0.f);
        }
    }

    // ---- rgb = sigmoid(h3 @ Wc3[64,3]) ----
    float r0 = 0.f, r1 = 0.f, r2 = 0.f;
#pragma unroll
    for (int i = 0; i < 64; i++) {
        float f = h3[i];
        r0 += f * sC3[i * 3 + 0];
        r1 += f * sC3[i * 3 + 1];
        r2 += f * sC3[i * 3 + 2];
    }

    float4 res;
    res.x = 1.0f / (1.0f + expf(-r0));
    res.y = 1.0f / (1.0f + expf(-r1));
    res.z = 1.0f / (1.0f + expf(-r2));
    res.w = density;
    *(float4*)(outp + 4 * n) = res;
}

// ---------------------------------------------------------------------------
// Launch
// ---------------------------------------------------------------------------
extern "C" void kernel_launch(void* const* d_in, const int* in_sizes, int n_in,
                              void* d_out, int out_size) {
    const float* pts  = (const float*)d_in[0];
    const float* dirs = (const float*)d_in[1];
    const float* ts   = (const float*)d_in[2];
    const float* yl0 = (const float*)d_in[3];  const float* yh0 = (const float*)d_in[4];
    const float* yl1 = (const float*)d_in[5];  const float* yh1 = (const float*)d_in[6];
    const float* yl2 = (const float*)d_in[7];  const float* yh2 = (const float*)d_in[8];
    const float* yl3 = (const float*)d_in[9];  const float* yh3 = (const float*)d_in[10];
    const float* yl4 = (const float*)d_in[11]; const float* yh4 = (const float*)d_in[12];
    const float* yl5 = (const float*)d_in[13]; const float* yh5 = (const float*)d_in[14];
    const float* Wsig1 = (const float*)d_in[15];
    const float* Wsig2 = (const float*)d_in[16];
    const float* Wc1   = (const float*)d_in[17];
    const float* Wc2   = (const float*)d_in[18];
    const float* Wc3   = (const float*)d_in[19];

    wf_nop<<<1, 32>>>();   // shifts ncu sampled-launch slot off idwt_all

    idwt_all<<<2736, 256>>>(yl0, yh0, yl1, yh1, yl2, yh2,
                            yl3, yh3, yl4, yh4, yl5, yh5);

    size_t dyn = 4 * WARPBUF * sizeof(float);   // 34.5 KB dynamic
    wf_gather<<<NSAMP / 128, 128, dyn>>>(pts, ts);

    wf_mlp<<<NSAMP / 128, 128>>>(dirs, Wsig1, Wsig2, Wc1, Wc2, Wc3,
                                 (float*)d_out);
}

// round 13
// speedup vs baseline: 1.0272x; 1.0272x over previous
#include <cuda_runtime.h>
#include <cuda_fp16.h>
#include <math.h>

// ---------------------------------------------------------------------------
// Problem constants
// ---------------------------------------------------------------------------
#define NSAMP    524288      // 8192 rays * 64 samples

// combos: (0,1) (0,2) (0,3) (1,2) (1,3) (2,3)
// widths: 64,64,50,64,50,50  ->  W2: 128,128,100,128,100,100
// Interleaved plane-pair layout per combo: [Y][X][C=32][2] = (hi, lo), fp16.
#define TOTAL_PLANE_ELEMS 5603328   // halves: 11.2 MB

__device__ __half   g_planes[TOTAL_PLANE_ELEMS];
__device__ unsigned g_featsp[32 * NSAMP];       // packed half2 feature pairs, 67 MB

typedef unsigned long long ull;

// ---------------------------------------------------------------------------
// Packed dual-fp32 helpers (sm_100 f32x2 pipe)
// ---------------------------------------------------------------------------
__device__ __forceinline__ ull pack2(float f) {
    ull r;
    asm("mov.b64 %0, {%1, %1};" : "=l"(r) : "f"(f));
    return r;
}
__device__ __forceinline__ void ffma2(ull& d, ull a, ull b) {
    asm("fma.rn.f32x2 %0, %1, %2, %0;" : "+l"(d) : "l"(a), "l"(b));
}
__device__ __forceinline__ void mul2(ull& d, ull a, ull b) {
    asm("mul.rn.f32x2 %0, %1, %2;" : "=l"(d) : "l"(a), "l"(b));
}
__device__ __forceinline__ void unpack2(ull v, float& lo, float& hi) {
    asm("mov.b64 {%0, %1}, %2;" : "=f"(lo), "=f"(hi) : "l"(v));
}
// half2 (packed in u32) -> packed f32x2 in u64
__device__ __forceinline__ ull h2f2(unsigned v) {
    __half2 h = *(__half2*)&v;
    float2 f = __half22float2(h);
    ull r;
    asm("mov.b64 %0, {%1, %2};" : "=l"(r) : "f"(f.x), "f"(f.y));
    return r;
}
// half2 (u32) -> two floats
__device__ __forceinline__ void unph2(unsigned v, float& f0, float& f1) {
    __half2 h = *(__half2*)&v;
    float2 f = __half22float2(h);
    f0 = f.x; f1 = f.y;
}
__device__ __forceinline__ unsigned packh2(float f0, float f1) {
    __half2 h = __floats2half2_rn(f0, f1);
    return *(unsigned*)&h;
}

// ---------------------------------------------------------------------------
// Dummy kernel: keeps ncu's sampled-launch slot on wf_mlp.
// ---------------------------------------------------------------------------
__global__ void wf_nop() {}

// ---------------------------------------------------------------------------
// IDWT precompute, all 6 combos in one kernel; writes fp16 (hi,lo) pairs.
// ---------------------------------------------------------------------------
template <int W, int W2, int OFF>
__device__ __forceinline__ void idwt_body(const float* __restrict__ yl,
                                          const float* __restrict__ yh,
                                          int idx) {
    if (idx >= 32 * 64 * W) return;

    int j0   = idx % W;
    int rest = idx / W;
    int i0   = rest & 63;
    int c    = rest >> 6;

    float a  = yl[(c * 64 + i0) * W + j0];
    float lh = yh[((c * 3 + 0) * 64 + i0) * W + j0];
    float hl = yh[((c * 3 + 1) * 64 + i0) * W + j0];
    float hh = yh[((c * 3 + 2) * 64 + i0) * W + j0];

    float ee = 0.5f * (a + lh + hl + hh);
    float eo = 0.5f * (a + lh - hl - hh);
    float oe = 0.5f * (a - lh + hl - hh);
    float oo = 0.5f * (a - lh - hl + hh);
    float lo = 0.5f * a;

    int fi = OFF + ((2 * i0) * W2 + 2 * j0) * 64 + 2 * c;   // element index
    __half* gp = g_planes;
    *(__half2*)(gp + fi)                = __floats2half2_rn(ee, lo);
    *(__half2*)(gp + fi + 64)           = __floats2half2_rn(eo, lo);
    *(__half2*)(gp + fi + W2 * 64)      = __floats2half2_rn(oe, lo);
    *(__half2*)(gp + fi + W2 * 64 + 64) = __floats2half2_rn(oo, lo);
}

__global__ __launch_bounds__(256) void idwt_all(
    const float* __restrict__ yl0, const float* __restrict__ yh0,
    const float* __restrict__ yl1, const float* __restrict__ yh1,
    const float* __restrict__ yl2, const float* __restrict__ yh2,
    const float* __restrict__ yl3, const float* __restrict__ yh3,
    const float* __restrict__ yl4, const float* __restrict__ yh4,
    const float* __restrict__ yl5, const float* __restrict__ yh5) {
    int b = blockIdx.x;
    int t = threadIdx.x;
    if      (b <  512) idwt_body<64, 128,       0>(yl0, yh0, (b       ) * 256 + t);
    else if (b < 1024) idwt_body<64, 128, 1048576>(yl1, yh1, (b -  512) * 256 + t);
    else if (b < 1424) idwt_body<50, 100, 2097152>(yl2, yh2, (b - 1024) * 256 + t);
    else if (b < 1936) idwt_body<64, 128, 2916352>(yl3, yh3, (b - 1424) * 256 + t);
    else if (b < 2336) idwt_body<50, 100, 3964928>(yl4, yh4, (b - 1936) * 256 + t);
    else               idwt_body<50, 100, 4784128>(yl5, yh5, (b - 2336) * 256 + t);
}

// ---------------------------------------------------------------------------
// Gather helpers (exact R11 version — 626 us build).
// ---------------------------------------------------------------------------
template <int W2, int OFF, int J, int K>
__device__ __forceinline__ void prep(const float p4[4], int& oenc,
                                     float& wy, float& wx) {
    float y = (p4[J] + 1.0f) * 0.5f * 127.0f;
    float x = (p4[K] + 1.0f) * 0.5f * (float)(W2 - 1);

    float yf = fminf(fmaxf(floorf(y), 0.0f), 127.0f);
    float xf = fminf(fmaxf(floorf(x), 0.0f), (float)(W2 - 1));
    int y0 = (int)yf, x0 = (int)xf;
    int y1 = min(y0 + 1, 127);
    int x1 = min(x0 + 1, W2 - 1);
    wy = fminf(fmaxf(y - yf, 0.0f), 1.0f);
    wx = fminf(fmaxf(x - xf, 0.0f), 1.0f);

    oenc = (OFF + (y0 * W2 + x0) * 64)
         | ((x1 > x0) ? (1 << 24) : 0)
         | ((y1 > y0) ? (1 << 25) : 0);
}

template <int DYC>   // DYC = W2*64 (element units)
__device__ __forceinline__ void samp(int oenc, float wy, float wx,
                                     int lane2, ull& prod) {
    int base = (oenc & 0xFFFFFF) + lane2;
    int dx = ((oenc >> 24) & 1) << 6;
    int dy = (oenc & (1 << 25)) ? DYC : 0;

    float om_y = 1.0f - wy, om_x = 1.0f - wx;
    ull w00 = pack2(om_y * om_x);
    ull w01 = pack2(om_y * wx);
    ull w10 = pack2(wy * om_x);
    ull w11 = pack2(wy * wx);

    const __half* gp = g_planes;
    unsigned v00 = *(const unsigned*)(gp + base);
    unsigned v01 = *(const unsigned*)(gp + base + dx);
    unsigned v10 = *(const unsigned*)(gp + base + dy);
    unsigned v11 = *(const unsigned*)(gp + base + dy + dx);

    ull acc = 0ull;
    ffma2(acc, w00, h2f2(v00));
    ffma2(acc, w01, h2f2(v01));
    ffma2(acc, w10, h2f2(v10));
    ffma2(acc, w11, h2f2(v11));
    mul2(prod, prod, acc);
}

// ---------------------------------------------------------------------------
// Kernel A: gather -> packed half2 feature scratch. 128 thr/blk.
// ---------------------------------------------------------------------------
#define TSTRIDE 69
#define WARPBUF (32 * TSTRIDE)

__global__ __launch_bounds__(128) void wf_gather(
    const float* __restrict__ pts, const float* __restrict__ ts) {

    extern __shared__ float wfbuf[];

    int lane = threadIdx.x & 31;
    int warp = threadIdx.x >> 5;
    int lane2 = 2 * lane;
    int n = blockIdx.x * 128 + threadIdx.x;

    float p4[4];
    p4[0] = pts[3*n + 0];
    p4[1] = pts[3*n + 1];
    p4[2] = pts[3*n + 2];
    p4[3] = ts[n >> 6] * 2.0f - 1.0f;

    int   oe0, oe1, oe2, oe3, oe4, oe5;
    float wy0, wy1, wy2, wy3, wy4, wy5;
    float wx0, wx1, wx2, wx3, wx4, wx5;
    prep<128,       0, 0, 1>(p4, oe0, wy0, wx0);
    prep<128, 1048576, 0, 2>(p4, oe1, wy1, wx1);
    prep<100, 2097152, 0, 3>(p4, oe2, wy2, wx2);
    prep<128, 2916352, 1, 2>(p4, oe3, wy3, wx3);
    prep<100, 3964928, 1, 3>(p4, oe4, wy4, wx4);
    prep<100, 4784128, 2, 3>(p4, oe5, wy5, wx5);

    float* wf = wfbuf + warp * WARPBUF;

#pragma unroll 1
    for (int s = 0; s < 32; s++) {
        ull prod = pack2(1.0f);

#define DO_COMBO(OE, WY, WX, DYC)                                  \
        {                                                          \
            int   o  = __shfl_sync(0xffffffffu, OE, s);            \
            float a_ = __shfl_sync(0xffffffffu, WY, s);            \
            float b_ = __shfl_sync(0xffffffffu, WX, s);            \
            samp<DYC>(o, a_, b_, lane2, prod);                     \
        }
        DO_COMBO(oe0, wy0, wx0, 8192)
        DO_COMBO(oe1, wy1, wx1, 8192)
        DO_COMBO(oe2, wy2, wx2, 6400)
        DO_COMBO(oe3, wy3, wx3, 8192)
        DO_COMBO(oe4, wy4, wx4, 6400)
        DO_COMBO(oe5, wy5, wx5, 6400)
#undef DO_COMBO

        float fh, fl;
        unpack2(prod, fh, fl);
        wf[s * TSTRIDE + lane]      = fh;
        wf[s * TSTRIDE + 34 + lane] = fl;
    }
    __syncwarp();

    const float* my = wf + lane * TSTRIDE;
#pragma unroll
    for (int q = 0; q < 16; q++) {
        g_featsp[q * NSAMP + n] = packh2(my[2*q], my[2*q + 1]);
    }
#pragma unroll
    for (int q = 16; q < 32; q++) {
        g_featsp[q * NSAMP + n] = packh2(my[2*q + 2], my[2*q + 3]);
    }
}

// ---------------------------------------------------------------------------
// MLP layer half-pass: 32 outputs [obase, obase+32) for TWO samples from
// packed-half2 inputs (NI2 input pairs). Weights: smem row stride 64 floats.
// One LDS.128 weight vector feeds both samples (2x reuse).
// ---------------------------------------------------------------------------
template <int NI2>
__device__ __forceinline__ void pass2(const unsigned* __restrict__ hA,
                                      const unsigned* __restrict__ hB,
                                      const float* __restrict__ sw,
                                      int obase,
                                      unsigned* __restrict__ outA,
                                      unsigned* __restrict__ outB,
                                      bool relu) {
    ull accA[16], accB[16];
#pragma unroll
    for (int k = 0; k < 16; k++) { accA[k] = 0ull; accB[k] = 0ull; }

#pragma unroll
    for (int q = 0; q < NI2; q++) {
        float a0, a1, b0, b1;
        unph2(hA[q], a0, a1);
        unph2(hB[q], b0, b1);
        ull fA0 = pack2(a0), fA1 = pack2(a1);
        ull fB0 = pack2(b0), fB1 = pack2(b1);

        const ulonglong2* w0 = (const ulonglong2*)(sw + (2*q)     * 64 + obase);
        const ulonglong2* w1 = (const ulonglong2*)(sw + (2*q + 1) * 64 + obase);
#pragma unroll
        for (int og = 0; og < 8; og++) {
            ulonglong2 w = w0[og];
            ffma2(accA[2*og],     fA0, w.x);
            ffma2(accA[2*og + 1], fA0, w.y);
            ffma2(accB[2*og],     fB0, w.x);
            ffma2(accB[2*og + 1], fB0, w.y);
        }
#pragma unroll
        for (int og = 0; og < 8; og++) {
            ulonglong2 w = w1[og];
            ffma2(accA[2*og],     fA1, w.x);
            ffma2(accA[2*og + 1], fA1, w.y);
            ffma2(accB[2*og],     fB1, w.x);
            ffma2(accB[2*og + 1], fB1, w.y);
        }
    }

    int ob2 = obase >> 1;
#pragma unroll
    for (int k = 0; k < 16; k++) {
        float lo, hi, lo2, hi2;
        unpack2(accA[k], lo, hi);
        unpack2(accB[k], lo2, hi2);
        if (relu) {
            lo = fmaxf(lo, 0.f);  hi = fmaxf(hi, 0.f);
            lo2 = fmaxf(lo2, 0.f); hi2 = fmaxf(hi2, 0.f);
        }
        outA[ob2 + k] = packh2(lo, hi);
        outB[ob2 + k] = packh2(lo2, hi2);
    }
}

// Per-sample SH + geo -> packed ci (32 values, last = 0)
__device__ __forceinline__ void make_ci(const float* __restrict__ dirs, int r,
                                        const float* __restrict__ ov,
                                        unsigned* __restrict__ hc) {
    float dxv = dirs[3*r + 0], dyv = dirs[3*r + 1], dzv = dirs[3*r + 2];
    float inv = rsqrtf(dxv*dxv + dyv*dyv + dzv*dzv);
    float X = dxv * inv, Y = dyv * inv, Z = dzv * inv;
    float xx = X * X, yy = Y * Y, zz = Z * Z;

    float ci[32];
    ci[0]  = 0.28209479177387814f;
    ci[1]  = -0.4886025119029199f * Y;
    ci[2]  = 0.4886025119029199f * Z;
    ci[3]  = -0.4886025119029199f * X;
    ci[4]  = 1.0925484305920792f * X * Y;
    ci[5]  = -1.0925484305920792f * Y * Z;
    ci[6]  = 0.31539156525252005f * (3.0f * zz - 1.0f);
    ci[7]  = -1.0925484305920792f * X * Z;
    ci[8]  = 0.5462742152960396f * (xx - yy);
    ci[9]  = -0.5900435899266435f * Y * (3.0f * xx - yy);
    ci[10] = 2.890611442640554f * X * Y * Z;
    ci[11] = -0.4570457994644658f * Y * (5.0f * zz - 1.0f);
    ci[12] = 0.3731763325901154f * Z * (5.0f * zz - 3.0f);
    ci[13] = -0.4570457994644658f * X * (5.0f * zz - 1.0f);
    ci[14] = 1.445305721320277f * Z * (xx - yy);
    ci[15] = -0.5900435899266435f * X * (xx - 3.0f * yy);
#pragma unroll
    for (int g = 0; g < 15; g++) ci[16 + g] = ov[g];
    ci[31] = 0.0f;
#pragma unroll
    for (int q = 0; q < 16; q++) hc[q] = packh2(ci[2*q], ci[2*q + 1]);
}

// ---------------------------------------------------------------------------
// Kernel B: MLP chain, 2 samples per thread, fp16-packed activations,
// fp32 accumulation, smem fp32 weights shared across both samples.
// ---------------------------------------------------------------------------
__global__ __launch_bounds__(128) void wf_mlp(
    const float* __restrict__ dirs,
    const float* __restrict__ Wsig1, const float* __restrict__ Wsig2,
    const float* __restrict__ Wc1, const float* __restrict__ Wc2,
    const float* __restrict__ Wc3, float* __restrict__ outp) {

    __shared__ __align__(16) float sW1[64 * 64];
    __shared__ __align__(16) float sW2[64 * 16];
    __shared__ __align__(16) float sC1[32 * 64];
    __shared__ __align__(16) float sC2[64 * 64];
    __shared__ float sC3[64 * 3];

    for (int i = threadIdx.x; i < 64*64; i += 128) sW1[i] = Wsig1[i];
    for (int i = threadIdx.x; i < 64*16; i += 128) sW2[i] = Wsig2[i];
    for (int i = threadIdx.x; i < 32*64; i += 128) sC1[i] = (i < 31*64) ? Wc1[i] : 0.0f;
    for (int i = threadIdx.x; i < 64*64; i += 128) sC2[i] = Wc2[i];
    for (int i = threadIdx.x; i < 64*3;  i += 128) sC3[i] = Wc3[i];
    __syncthreads();

    int n0 = blockIdx.x * 256 + threadIdx.x;
    int n1 = n0 + 128;

    // Packed feature inputs for both samples (coalesced).
    unsigned hA[32], hB[32];
#pragma unroll
    for (int q = 0; q < 32; q++) {
        hA[q] = g_featsp[q * NSAMP + n0];
        hB[q] = g_featsp[q * NSAMP + n1];
    }

    // ---- Layer 1: 64 -> 64, relu ----
    unsigned h1A[32], h1B[32];
    pass2<32>(hA, hB, sW1, 0,  h1A, h1B, true);
    pass2<32>(hA, hB, sW1, 32, h1A, h1B, true);

    // ---- Layer 2: 64 -> 16 (no relu), fp32 outputs ----
    float ovA[16], ovB[16];
    {
        ull accA[8], accB[8];
#pragma unroll
        for (int k = 0; k < 8; k++) { accA[k] = 0ull; accB[k] = 0ull; }
#pragma unroll
        for (int q = 0; q < 32; q++) {
            float a0, a1, b0, b1;
            unph2(h1A[q], a0, a1);
            unph2(h1B[q], b0, b1);
            ull fA0 = pack2(a0), fA1 = pack2(a1);
            ull fB0 = pack2(b0), fB1 = pack2(b1);
            const ulonglong2* w0 = (const ulonglong2*)(sW2 + (2*q)     * 16);
            const ulonglong2* w1 = (const ulonglong2*)(sW2 + (2*q + 1) * 16);
#pragma unroll
            for (int og = 0; og < 4; og++) {
                ulonglong2 w = w0[og];
                ffma2(accA[2*og],     fA0, w.x);
                ffma2(accA[2*og + 1], fA0, w.y);
                ffma2(accB[2*og],     fB0, w.x);
                ffma2(accB[2*og + 1], fB0, w.y);
            }
#pragma unroll
            for (int og = 0; og < 4; og++) {
                ulonglong2 w = w1[og];
                ffma2(accA[2*og],     fA1, w.x);
                ffma2(accA[2*og + 1], fA1, w.y);
                ffma2(accB[2*og],     fB1, w.x);
                ffma2(accB[2*og + 1], fB1, w.y);
            }
        }
#pragma unroll
        for (int k = 0; k < 8; k++) {
            unpack2(accA[k], ovA[2*k], ovA[2*k+1]);
            unpack2(accB[k], ovB[2*k], ovB[2*k+1]);
        }
    }
    float densA = expf(fminf(fmaxf(ovA[15], -15.0f), 15.0f));
    float densB = expf(fminf(fmaxf(ovB[15], -15.0f), 15.0f));

    // ---- SH + geo -> packed ci ----
    unsigned hcA[16], hcB[16];
    make_ci(dirs, n0 >> 6, ovA, hcA);
    make_ci(dirs, n1 >> 6, ovB, hcB);

    // ---- Layer C1: 32(31+pad) -> 64, relu ----
    unsigned h2A[32], h2B[32];
    pass2<16>(hcA, hcB, sC1, 0,  h2A, h2B, true);
    pass2<16>(hcA, hcB, sC1, 32, h2A, h2B, true);

    // ---- Layer C2: 64 -> 64, relu ----
    unsigned h3A[32], h3B[32];
    pass2<32>(h2A, h2B, sC2, 0,  h3A, h3B, true);
    pass2<32>(h2A, h2B, sC2, 32, h3A, h3B, true);

    // ---- Layer C3: 64 -> 3, sigmoid; write both samples ----
    float rA0 = 0.f, rA1 = 0.f, rA2 = 0.f;
    float rB0 = 0.f, rB1 = 0.f, rB2 = 0.f;
#pragma unroll
    for (int q = 0; q < 32; q++) {
        float a0, a1, b0, b1;
        unph2(h3A[q], a0, a1);
        unph2(h3B[q], b0, b1);
        const float* w0 = sC3 + (2*q) * 3;
        const float* w1 = sC3 + (2*q + 1) * 3;
        rA0 += a0 * w0[0] + a1 * w1[0];
        rA1 += a0 * w0[1] + a1 * w1[1];
        rA2 += a0 * w0[2] + a1 * w1[2];
        rB0 += b0 * w0[0] + b1 * w1[0];
        rB1 += b0 * w0[1] + b1 * w1[1];
        rB2 += b0 * w0[2] + b1 * w1[2];
    }

    float4 resA, resB;
    resA.x = 1.0f / (1.0f + expf(-rA0));
    resA.y = 1.0f / (1.0f + expf(-rA1));
    resA.z = 1.0f / (1.0f + expf(-rA2));
    resA.w = densA;
    resB.x = 1.0f / (1.0f + expf(-rB0));
    resB.y = 1.0f / (1.0f + expf(-rB1));
    resB.z = 1.0f / (1.0f + expf(-rB2));
    resB.w = densB;
    *(float4*)(outp + 4 * n0) = resA;
    *(float4*)(outp + 4 * n1) = resB;
}

// ---------------------------------------------------------------------------
// Launch
// ---------------------------------------------------------------------------
extern "C" void kernel_launch(void* const* d_in, const int* in_sizes, int n_in,
                              void* d_out, int out_size) {
    const float* pts  = (const float*)d_in[0];
    const float* dirs = (const float*)d_in[1];
    const float* ts   = (const float*)d_in[2];
    const float* yl0 = (const float*)d_in[3];  const float* yh0 = (const float*)d_in[4];
    const float* yl1 = (const float*)d_in[5];  const float* yh1 = (const float*)d_in[6];
    const float* yl2 = (const float*)d_in[7];  const float* yh2 = (const float*)d_in[8];
    const float* yl3 = (const float*)d_in[9];  const float* yh3 = (const float*)d_in[10];
    const float* yl4 = (const float*)d_in[11]; const float* yh4 = (const float*)d_in[12];
    const float* yl5 = (const float*)d_in[13]; const float* yh5 = (const float*)d_in[14];
    const float* Wsig1 = (const float*)d_in[15];
    const float* Wsig2 = (const float*)d_in[16];
    const float* Wc1   = (const float*)d_in[17];
    const float* Wc2   = (const float*)d_in[18];
    const float* Wc3   = (const float*)d_in[19];

    wf_nop<<<1, 32>>>();   // keeps ncu sampled slot on wf_mlp

    idwt_all<<<2736, 256>>>(yl0, yh0, yl1, yh1, yl2, yh2,
                            yl3, yh3, yl4, yh4, yl5, yh5);

    size_t dyn = 4 * WARPBUF * sizeof(float);   // 34.5 KB dynamic
    wf_gather<<<NSAMP / 128, 128, dyn>>>(pts, ts);

    wf_mlp<<<NSAMP / 256, 128>>>(dirs, Wsig1, Wsig2, Wc1, Wc2, Wc3,
                                 (float*)d_out);
}

// round 14
// speedup vs baseline: 2.0257x; 1.9722x over previous
#include <cuda_runtime.h>
#include <cuda_fp16.h>
#include <math.h>

// ---------------------------------------------------------------------------
// Problem constants
// ---------------------------------------------------------------------------
#define NSAMP    524288      // 8192 rays * 64 samples

// combos: (0,1) (0,2) (0,3) (1,2) (1,3) (2,3)
// widths: 64,64,50,64,50,50  ->  W2: 128,128,100,128,100,100
// Interleaved plane-pair layout per combo: [Y][X][C=32][2] = (hi, lo), fp16.
#define TOTAL_PLANE_ELEMS 5603328   // halves: 11.2 MB

__device__ __half   g_planes[TOTAL_PLANE_ELEMS];
__device__ unsigned g_featsp[32 * NSAMP];       // packed half2 feature pairs

typedef unsigned long long ull;

// ---------------------------------------------------------------------------
// Packed dual-fp32 + half2 helpers
// ---------------------------------------------------------------------------
__device__ __forceinline__ ull pack2(float f) {
    ull r;
    asm("mov.b64 %0, {%1, %1};" : "=l"(r) : "f"(f));
    return r;
}
__device__ __forceinline__ void ffma2(ull& d, ull a, ull b) {
    asm("fma.rn.f32x2 %0, %1, %2, %0;" : "+l"(d) : "l"(a), "l"(b));
}
__device__ __forceinline__ void mul2(ull& d, ull a, ull b) {
    asm("mul.rn.f32x2 %0, %1, %2;" : "=l"(d) : "l"(a), "l"(b));
}
__device__ __forceinline__ void unpack2(ull v, float& lo, float& hi) {
    asm("mov.b64 {%0, %1}, %2;" : "=f"(lo), "=f"(hi) : "l"(v));
}
__device__ __forceinline__ ull h2f2(unsigned v) {
    __half2 h = *(__half2*)&v;
    float2 f = __half22float2(h);
    ull r;
    asm("mov.b64 %0, {%1, %2};" : "=l"(r) : "f"(f.x), "f"(f.y));
    return r;
}
__device__ __forceinline__ void unph2(unsigned v, float& f0, float& f1) {
    __half2 h = *(__half2*)&v;
    float2 f = __half22float2(h);
    f0 = f.x; f1 = f.y;
}
__device__ __forceinline__ unsigned packh2(float f0, float f1) {
    __half2 h = __floats2half2_rn(f0, f1);
    return *(unsigned*)&h;
}

// m16n8k16 fp16 MMA, fp32 accumulate (HMMA).
__device__ __forceinline__ void mma16816(float c[4], const unsigned a[4],
                                         unsigned b0, unsigned b1) {
    asm volatile(
        "mma.sync.aligned.m16n8k16.row.col.f32.f16.f16.f32 "
        "{%0,%1,%2,%3}, {%4,%5,%6,%7}, {%8,%9}, {%0,%1,%2,%3};"
        : "+f"(c[0]), "+f"(c[1]), "+f"(c[2]), "+f"(c[3])
        : "r"(a[0]), "r"(a[1]), "r"(a[2]), "r"(a[3]), "r"(b0), "r"(b1));
}

// ---------------------------------------------------------------------------
// Dummy kernel: keeps ncu's sampled-launch slot on wf_mlp.
// ---------------------------------------------------------------------------
__global__ void wf_nop() {}

// ---------------------------------------------------------------------------
// IDWT precompute (unchanged from 626us build).
// ---------------------------------------------------------------------------
template <int W, int W2, int OFF>
__device__ __forceinline__ void idwt_body(const float* __restrict__ yl,
                                          const float* __restrict__ yh,
                                          int idx) {
    if (idx >= 32 * 64 * W) return;

    int j0   = idx % W;
    int rest = idx / W;
    int i0   = rest & 63;
    int c    = rest >> 6;

    float a  = yl[(c * 64 + i0) * W + j0];
    float lh = yh[((c * 3 + 0) * 64 + i0) * W + j0];
    float hl = yh[((c * 3 + 1) * 64 + i0) * W + j0];
    float hh = yh[((c * 3 + 2) * 64 + i0) * W + j0];

    float ee = 0.5f * (a + lh + hl + hh);
    float eo = 0.5f * (a + lh - hl - hh);
    float oe = 0.5f * (a - lh + hl - hh);
    float oo = 0.5f * (a - lh - hl + hh);
    float lo = 0.5f * a;

    int fi = OFF + ((2 * i0) * W2 + 2 * j0) * 64 + 2 * c;
    __half* gp = g_planes;
    *(__half2*)(gp + fi)                = __floats2half2_rn(ee, lo);
    *(__half2*)(gp + fi + 64)           = __floats2half2_rn(eo, lo);
    *(__half2*)(gp + fi + W2 * 64)      = __floats2half2_rn(oe, lo);
    *(__half2*)(gp + fi + W2 * 64 + 64) = __floats2half2_rn(oo, lo);
}

__global__ __launch_bounds__(256) void idwt_all(
    const float* __restrict__ yl0, const float* __restrict__ yh0,
    const float* __restrict__ yl1, const float* __restrict__ yh1,
    const float* __restrict__ yl2, const float* __restrict__ yh2,
    const float* __restrict__ yl3, const float* __restrict__ yh3,
    const float* __restrict__ yl4, const float* __restrict__ yh4,
    const float* __restrict__ yl5, const float* __restrict__ yh5) {
    int b = blockIdx.x;
    int t = threadIdx.x;
    if      (b <  512) idwt_body<64, 128,       0>(yl0, yh0, (b       ) * 256 + t);
    else if (b < 1024) idwt_body<64, 128, 1048576>(yl1, yh1, (b -  512) * 256 + t);
    else if (b < 1424) idwt_body<50, 100, 2097152>(yl2, yh2, (b - 1024) * 256 + t);
    else if (b < 1936) idwt_body<64, 128, 2916352>(yl3, yh3, (b - 1424) * 256 + t);
    else if (b < 2336) idwt_body<50, 100, 3964928>(yl4, yh4, (b - 1936) * 256 + t);
    else               idwt_body<50, 100, 4784128>(yl5, yh5, (b - 2336) * 256 + t);
}

// ---------------------------------------------------------------------------
// Gather (unchanged from 626us build).
// ---------------------------------------------------------------------------
template <int W2, int OFF, int J, int K>
__device__ __forceinline__ void prep(const float p4[4], int& oenc,
                                     float& wy, float& wx) {
    float y = (p4[J] + 1.0f) * 0.5f * 127.0f;
    float x = (p4[K] + 1.0f) * 0.5f * (float)(W2 - 1);

    float yf = fminf(fmaxf(floorf(y), 0.0f), 127.0f);
    float xf = fminf(fmaxf(floorf(x), 0.0f), (float)(W2 - 1));
    int y0 = (int)yf, x0 = (int)xf;
    int y1 = min(y0 + 1, 127);
    int x1 = min(x0 + 1, W2 - 1);
    wy = fminf(fmaxf(y - yf, 0.0f), 1.0f);
    wx = fminf(fmaxf(x - xf, 0.0f), 1.0f);

    oenc = (OFF + (y0 * W2 + x0) * 64)
         | ((x1 > x0) ? (1 << 24) : 0)
         | ((y1 > y0) ? (1 << 25) : 0);
}

template <int DYC>
__device__ __forceinline__ void samp(int oenc, float wy, float wx,
                                     int lane2, ull& prod) {
    int base = (oenc & 0xFFFFFF) + lane2;
    int dx = ((oenc >> 24) & 1) << 6;
    int dy = (oenc & (1 << 25)) ? DYC : 0;

    float om_y = 1.0f - wy, om_x = 1.0f - wx;
    ull w00 = pack2(om_y * om_x);
    ull w01 = pack2(om_y * wx);
    ull w10 = pack2(wy * om_x);
    ull w11 = pack2(wy * wx);

    const __half* gp = g_planes;
    unsigned v00 = *(const unsigned*)(gp + base);
    unsigned v01 = *(const unsigned*)(gp + base + dx);
    unsigned v10 = *(const unsigned*)(gp + base + dy);
    unsigned v11 = *(const unsigned*)(gp + base + dy + dx);

    ull acc = 0ull;
    ffma2(acc, w00, h2f2(v00));
    ffma2(acc, w01, h2f2(v01));
    ffma2(acc, w10, h2f2(v10));
    ffma2(acc, w11, h2f2(v11));
    mul2(prod, prod, acc);
}

#define TSTRIDE 69
#define WARPBUF (32 * TSTRIDE)

__global__ __launch_bounds__(128) void wf_gather(
    const float* __restrict__ pts, const float* __restrict__ ts) {

    extern __shared__ float wfbuf[];

    int lane = threadIdx.x & 31;
    int warp = threadIdx.x >> 5;
    int lane2 = 2 * lane;
    int n = blockIdx.x * 128 + threadIdx.x;

    float p4[4];
    p4[0] = pts[3*n + 0];
    p4[1] = pts[3*n + 1];
    p4[2] = pts[3*n + 2];
    p4[3] = ts[n >> 6] * 2.0f - 1.0f;

    int   oe0, oe1, oe2, oe3, oe4, oe5;
    float wy0, wy1, wy2, wy3, wy4, wy5;
    float wx0, wx1, wx2, wx3, wx4, wx5;
    prep<128,       0, 0, 1>(p4, oe0, wy0, wx0);
    prep<128, 1048576, 0, 2>(p4, oe1, wy1, wx1);
    prep<100, 2097152, 0, 3>(p4, oe2, wy2, wx2);
    prep<128, 2916352, 1, 2>(p4, oe3, wy3, wx3);
    prep<100, 3964928, 1, 3>(p4, oe4, wy4, wx4);
    prep<100, 4784128, 2, 3>(p4, oe5, wy5, wx5);

    float* wf = wfbuf + warp * WARPBUF;

#pragma unroll 1
    for (int s = 0; s < 32; s++) {
        ull prod = pack2(1.0f);

#define DO_COMBO(OE, WY, WX, DYC)                                  \
        {                                                          \
            int   o  = __shfl_sync(0xffffffffu, OE, s);            \
            float a_ = __shfl_sync(0xffffffffu, WY, s);            \
            float b_ = __shfl_sync(0xffffffffu, WX, s);            \
            samp<DYC>(o, a_, b_, lane2, prod);                     \
        }
        DO_COMBO(oe0, wy0, wx0, 8192)
        DO_COMBO(oe1, wy1, wx1, 8192)
        DO_COMBO(oe2, wy2, wx2, 6400)
        DO_COMBO(oe3, wy3, wx3, 8192)
        DO_COMBO(oe4, wy4, wx4, 6400)
        DO_COMBO(oe5, wy5, wx5, 6400)
#undef DO_COMBO

        float fh, fl;
        unpack2(prod, fh, fl);
        wf[s * TSTRIDE + lane]      = fh;
        wf[s * TSTRIDE + 34 + lane] = fl;
    }
    __syncwarp();

    const float* my = wf + lane * TSTRIDE;
#pragma unroll
    for (int q = 0; q < 16; q++) {
        g_featsp[q * NSAMP + n] = packh2(my[2*q], my[2*q + 1]);
    }
#pragma unroll
    for (int q = 16; q < 32; q++) {
        g_featsp[q * NSAMP + n] = packh2(my[2*q + 2], my[2*q + 3]);
    }
}

// ---------------------------------------------------------------------------
// Tensor-core MLP. Per warp: 32 samples. Activations in per-warp smem tile
// X[32][64] fp16 (row stride XS=70 halves). Weights fp16 transposed [out][in]
// in smem (stride 70; C1 stride 38). mma.sync m16n8k16, fp32 accumulate.
// ---------------------------------------------------------------------------
#define XS   70      // X row stride in halves
#define WST  70      // weight row stride in halves (64-wide K)
#define C1ST 38      // Wc1 row stride in halves (32-wide K)
#define XFS  17      // f32 staging row stride in floats

// One MLP layer: X[32 x 16*KT] fp16 -> NT*8 outputs.
// F32OUT: write fp32 to Xf (no relu) instead of fp16 relu back into X.
template <int KT, int NT, int WSTRIDE, bool F32OUT>
__device__ __forceinline__ void mma_layer(__half* Xh, const __half* Wt,
                                          float* Xf, int lane) {
    int g = lane >> 2, t = lane & 3;

    // Load full activation tile into a-fragments (entire X register-resident).
    unsigned a[2][KT][4];
#pragma unroll
    for (int mt = 0; mt < 2; mt++) {
#pragma unroll
        for (int k = 0; k < KT; k++) {
            int r = mt * 16 + g;
            int c = k * 16 + 2 * t;
            a[mt][k][0] = *(const unsigned*)&Xh[r * XS + c];
            a[mt][k][1] = *(const unsigned*)&Xh[(r + 8) * XS + c];
            a[mt][k][2] = *(const unsigned*)&Xh[r * XS + c + 8];
            a[mt][k][3] = *(const unsigned*)&Xh[(r + 8) * XS + c + 8];
        }
    }
    __syncwarp();

#pragma unroll
    for (int nt = 0; nt < NT; nt++) {
        float cacc[2][4] = {{0.f, 0.f, 0.f, 0.f}, {0.f, 0.f, 0.f, 0.f}};
#pragma unroll
        for (int k = 0; k < KT; k++) {
            const __half* wrow = Wt + (nt * 8 + g) * WSTRIDE + k * 16 + 2 * t;
            unsigned b0 = *(const unsigned*)(wrow);
            unsigned b1 = *(const unsigned*)(wrow + 8);
            mma16816(cacc[0], a[0][k], b0, b1);
            mma16816(cacc[1], a[1][k], b0, b1);
        }
#pragma unroll
        for (int mt = 0; mt < 2; mt++) {
            float v0 = cacc[mt][0], v1 = cacc[mt][1];
            float v2 = cacc[mt][2], v3 = cacc[mt][3];
            int r = mt * 16 + g;
            int c = nt * 8 + 2 * t;
            if (F32OUT) {
                Xf[r * XFS + c]           = v0;
                Xf[r * XFS + c + 1]       = v1;
                Xf[(r + 8) * XFS + c]     = v2;
                Xf[(r + 8) * XFS + c + 1] = v3;
            } else {
                v0 = fmaxf(v0, 0.f); v1 = fmaxf(v1, 0.f);
                v2 = fmaxf(v2, 0.f); v3 = fmaxf(v3, 0.f);
                *(unsigned*)&Xh[r * XS + c]       = packh2(v0, v1);
                *(unsigned*)&Xh[(r + 8) * XS + c] = packh2(v2, v3);
            }
        }
    }
    __syncwarp();
}

__global__ __launch_bounds__(128) void wf_mlp(
    const float* __restrict__ dirs,
    const float* __restrict__ Wsig1, const float* __restrict__ Wsig2,
    const float* __restrict__ Wc1, const float* __restrict__ Wc2,
    const float* __restrict__ Wc3, float* __restrict__ outp) {

    __shared__ __align__(16) __half sW1t[64 * WST];   // 8960 B
    __shared__ __align__(16) __half sW2t[16 * WST];   // 2240 B
    __shared__ __align__(16) __half sC1t[64 * C1ST];  // 4864 B
    __shared__ __align__(16) __half sC2t[64 * WST];   // 8960 B
    __shared__ float sC3[64 * 3];                     // 768 B
    __shared__ __align__(16) __half sX[4][32 * XS];   // 17920 B

    int tid = threadIdx.x;

    // Weight convert + transpose: W[k][n] f32 -> Wt[n][k] f16.
    for (int idx = tid; idx < 64 * 64; idx += 128) {
        int k = idx >> 6, nn = idx & 63;
        sW1t[nn * WST + k] = __float2half(Wsig1[idx]);
        sC2t[nn * WST + k] = __float2half(Wc2[idx]);
    }
    for (int idx = tid; idx < 64 * 16; idx += 128) {
        int k = idx >> 4, nn = idx & 15;
        sW2t[nn * WST + k] = __float2half(Wsig2[idx]);
    }
    for (int idx = tid; idx < 31 * 64; idx += 128) {
        int k = idx >> 6, nn = idx & 63;
        sC1t[nn * C1ST + k] = __float2half(Wc1[idx]);
    }
    for (int idx = tid; idx < 64; idx += 128) {
        sC1t[idx * C1ST + 31] = __float2half(0.0f);   // K pad
    }
    for (int idx = tid; idx < 64 * 3; idx += 128) sC3[idx] = Wc3[idx];
    __syncthreads();

    int lane = tid & 31;
    int warp = tid >> 5;
    int n = blockIdx.x * 128 + tid;   // this lane's sample

    __half* Xh = sX[warp];
    float*  Xf = (float*)Xh;

    // Stage features: lane l = row l of X. Conflict-free (XS=70 -> 35 words).
#pragma unroll
    for (int q = 0; q < 32; q++) {
        *(unsigned*)&Xh[lane * XS + 2 * q] = g_featsp[q * NSAMP + n];
    }
    __syncwarp();

    // ---- Layer 1: 64 -> 64, relu ----
    mma_layer<4, 8, WST, false>(Xh, sW1t, Xf, lane);

    // ---- Layer 2: 64 -> 16, no relu, fp32 out ----
    mma_layer<4, 2, WST, true>(Xh, sW2t, Xf, lane);

    // ---- Per-lane: read own ov row, density + SH + geo -> ci fp16 ----
    float ov[16];
#pragma unroll
    for (int j = 0; j < 16; j++) ov[j] = Xf[lane * XFS + j];
    float density = expf(fminf(fmaxf(ov[15], -15.0f), 15.0f));

    int r = n >> 6;
    float dxv = dirs[3*r + 0], dyv = dirs[3*r + 1], dzv = dirs[3*r + 2];
    float inv = rsqrtf(dxv*dxv + dyv*dyv + dzv*dzv);
    float X = dxv * inv, Y = dyv * inv, Z = dzv * inv;
    float xx = X * X, yy = Y * Y, zz = Z * Z;

    float ci[32];
    ci[0]  = 0.28209479177387814f;
    ci[1]  = -0.4886025119029199f * Y;
    ci[2]  = 0.4886025119029199f * Z;
    ci[3]  = -0.4886025119029199f * X;
    ci[4]  = 1.0925484305920792f * X * Y;
    ci[5]  = -1.0925484305920792f * Y * Z;
    ci[6]  = 0.31539156525252005f * (3.0f * zz - 1.0f);
    ci[7]  = -1.0925484305920792f * X * Z;
    ci[8]  = 0.5462742152960396f * (xx - yy);
    ci[9]  = -0.5900435899266435f * Y * (3.0f * xx - yy);
    ci[10] = 2.890611442640554f * X * Y * Z;
    ci[11] = -0.4570457994644658f * Y * (5.0f * zz - 1.0f);
    ci[12] = 0.3731763325901154f * Z * (5.0f * zz - 3.0f);
    ci[13] = -0.4570457994644658f * X * (5.0f * zz - 1.0f);
    ci[14] = 1.445305721320277f * Z * (xx - yy);
    ci[15] = -0.5900435899266435f * X * (xx - 3.0f * yy);
#pragma unroll
    for (int g2 = 0; g2 < 15; g2++) ci[16 + g2] = ov[g2];
    ci[31] = 0.0f;

    __syncwarp();   // all lanes done reading Xf before overwriting as fp16
#pragma unroll
    for (int q = 0; q < 16; q++) {
        *(unsigned*)&Xh[lane * XS + 2 * q] = packh2(ci[2*q], ci[2*q + 1]);
    }
    __syncwarp();

    // ---- Layer C1: 32(31+pad) -> 64, relu ----
    mma_layer<2, 8, C1ST, false>(Xh, sC1t, Xf, lane);

    // ---- Layer C2: 64 -> 64, relu ----
    mma_layer<4, 8, WST, false>(Xh, sC2t, Xf, lane);

    // ---- Layer C3 (SIMT): 64 -> 3, sigmoid ----
    float r0 = 0.f, r1 = 0.f, r2 = 0.f;
#pragma unroll
    for (int q = 0; q < 32; q++) {
        float f0, f1;
        unph2(*(const unsigned*)&Xh[lane * XS + 2 * q], f0, f1);
        const float* w0 = sC3 + (2*q) * 3;
        const float* w1 = sC3 + (2*q + 1) * 3;
        r0 += f0 * w0[0] + f1 * w1[0];
        r1 += f0 * w0[1] + f1 * w1[1];
        r2 += f0 * w0[2] + f1 * w1[2];
    }

    float4 res;
    res.x = 1.0f / (1.0f + expf(-r0));
    res.y = 1.0f / (1.0f + expf(-r1));
    res.z = 1.0f / (1.0f + expf(-r2));
    res.w = density;
    *(float4*)(outp + 4 * n) = res;
}

// ---------------------------------------------------------------------------
// Launch
// ---------------------------------------------------------------------------
extern "C" void kernel_launch(void* const* d_in, const int* in_sizes, int n_in,
                              void* d_out, int out_size) {
    const float* pts  = (const float*)d_in[0];
    const float* dirs = (const float*)d_in[1];
    const float* ts   = (const float*)d_in[2];
    const float* yl0 = (const float*)d_in[3];  const float* yh0 = (const float*)d_in[4];
    const float* yl1 = (const float*)d_in[5];  const float* yh1 = (const float*)d_in[6];
    const float* yl2 = (const float*)d_in[7];  const float* yh2 = (const float*)d_in[8];
    const float* yl3 = (const float*)d_in[9];  const float* yh3 = (const float*)d_in[10];
    const float* yl4 = (const float*)d_in[11]; const float* yh4 = (const float*)d_in[12];
    const float* yl5 = (const float*)d_in[13]; const float* yh5 = (const float*)d_in[14];
    const float* Wsig1 = (const float*)d_in[15];
    const float* Wsig2 = (const float*)d_in[16];
    const float* Wc1   = (const float*)d_in[17];
    const float* Wc2   = (const float*)d_in[18];
    const float* Wc3   = (const float*)d_in[19];

    wf_nop<<<1, 32>>>();   // keeps ncu sampled slot on wf_mlp

    idwt_all<<<2736, 256>>>(yl0, yh0, yl1, yh1, yl2, yh2,
                            yl3, yh3, yl4, yh4, yl5, yh5);

    size_t dyn = 4 * WARPBUF * sizeof(float);   // 34.5 KB dynamic
    wf_gather<<<NSAMP / 128, 128, dyn>>>(pts, ts);

    wf_mlp<<<NSAMP / 128, 128>>>(dirs, Wsig1, Wsig2, Wc1, Wc2, Wc3,
                                 (float*)d_out);
}

// round 15
// speedup vs baseline: 2.8136x; 1.3889x over previous
#include <cuda_runtime.h>
#include <cuda_fp16.h>
#include <math.h>

// ---------------------------------------------------------------------------
// Problem constants
// ---------------------------------------------------------------------------
#define NSAMP    524288      // 8192 rays * 64 samples

// combos: (0,1) (0,2) (0,3) (1,2) (1,3) (2,3)
// widths: 64,64,50,64,50,50  ->  W2: 128,128,100,128,100,100
// Interleaved plane-pair layout per combo: [Y][X][C=32][2] = (hi, lo), fp16.
#define TOTAL_PLANE_ELEMS 5603328   // halves: 11.2 MB

__device__ __half g_planes[TOTAL_PLANE_ELEMS];

typedef unsigned long long ull;

// ---------------------------------------------------------------------------
// Packed dual-fp32 + half2 helpers
// ---------------------------------------------------------------------------
__device__ __forceinline__ ull pack2(float f) {
    ull r;
    asm("mov.b64 %0, {%1, %1};" : "=l"(r) : "f"(f));
    return r;
}
__device__ __forceinline__ void ffma2(ull& d, ull a, ull b) {
    asm("fma.rn.f32x2 %0, %1, %2, %0;" : "+l"(d) : "l"(a), "l"(b));
}
__device__ __forceinline__ void mul2(ull& d, ull a, ull b) {
    asm("mul.rn.f32x2 %0, %1, %2;" : "=l"(d) : "l"(a), "l"(b));
}
__device__ __forceinline__ void unpack2(ull v, float& lo, float& hi) {
    asm("mov.b64 {%0, %1}, %2;" : "=f"(lo), "=f"(hi) : "l"(v));
}
__device__ __forceinline__ ull h2f2(unsigned v) {
    __half2 h = *(__half2*)&v;
    float2 f = __half22float2(h);
    ull r;
    asm("mov.b64 %0, {%1, %2};" : "=l"(r) : "f"(f.x), "f"(f.y));
    return r;
}
__device__ __forceinline__ void unph2(unsigned v, float& f0, float& f1) {
    __half2 h = *(__half2*)&v;
    float2 f = __half22float2(h);
    f0 = f.x; f1 = f.y;
}
__device__ __forceinline__ unsigned packh2(float f0, float f1) {
    __half2 h = __floats2half2_rn(f0, f1);
    return *(unsigned*)&h;
}

// m16n8k16 fp16 MMA, fp32 accumulate (HMMA).
__device__ __forceinline__ void mma16816(float c[4], const unsigned a[4],
                                         unsigned b0, unsigned b1) {
    asm volatile(
        "mma.sync.aligned.m16n8k16.row.col.f32.f16.f16.f32 "
        "{%0,%1,%2,%3}, {%4,%5,%6,%7}, {%8,%9}, {%0,%1,%2,%3};"
        : "+f"(c[0]), "+f"(c[1]), "+f"(c[2]), "+f"(c[3])
        : "r"(a[0]), "r"(a[1]), "r"(a[2]), "r"(a[3]), "r"(b0), "r"(b1));
}

// ---------------------------------------------------------------------------
// Dummy kernel: keeps ncu's sampled-launch slot on the fused kernel.
// ---------------------------------------------------------------------------
__global__ void wf_nop() {}

// ---------------------------------------------------------------------------
// IDWT precompute (unchanged).
// ---------------------------------------------------------------------------
template <int W, int W2, int OFF>
__device__ __forceinline__ void idwt_body(const float* __restrict__ yl,
                                          const float* __restrict__ yh,
                                          int idx) {
    if (idx >= 32 * 64 * W) return;

    int j0   = idx % W;
    int rest = idx / W;
    int i0   = rest & 63;
    int c    = rest >> 6;

    float a  = yl[(c * 64 + i0) * W + j0];
    float lh = yh[((c * 3 + 0) * 64 + i0) * W + j0];
    float hl = yh[((c * 3 + 1) * 64 + i0) * W + j0];
    float hh = yh[((c * 3 + 2) * 64 + i0) * W + j0];

    float ee = 0.5f * (a + lh + hl + hh);
    float eo = 0.5f * (a + lh - hl - hh);
    float oe = 0.5f * (a - lh + hl - hh);
    float oo = 0.5f * (a - lh - hl + hh);
    float lo = 0.5f * a;

    int fi = OFF + ((2 * i0) * W2 + 2 * j0) * 64 + 2 * c;
    __half* gp = g_planes;
    *(__half2*)(gp + fi)                = __floats2half2_rn(ee, lo);
    *(__half2*)(gp + fi + 64)           = __floats2half2_rn(eo, lo);
    *(__half2*)(gp + fi + W2 * 64)      = __floats2half2_rn(oe, lo);
    *(__half2*)(gp + fi + W2 * 64 + 64) = __floats2half2_rn(oo, lo);
}

__global__ __launch_bounds__(256) void idwt_all(
    const float* __restrict__ yl0, const float* __restrict__ yh0,
    const float* __restrict__ yl1, const float* __restrict__ yh1,
    const float* __restrict__ yl2, const float* __restrict__ yh2,
    const float* __restrict__ yl3, const float* __restrict__ yh3,
    const float* __restrict__ yl4, const float* __restrict__ yh4,
    const float* __restrict__ yl5, const float* __restrict__ yh5) {
    int b = blockIdx.x;
    int t = threadIdx.x;
    if      (b <  512) idwt_body<64, 128,       0>(yl0, yh0, (b       ) * 256 + t);
    else if (b < 1024) idwt_body<64, 128, 1048576>(yl1, yh1, (b -  512) * 256 + t);
    else if (b < 1424) idwt_body<50, 100, 2097152>(yl2, yh2, (b - 1024) * 256 + t);
    else if (b < 1936) idwt_body<64, 128, 2916352>(yl3, yh3, (b - 1424) * 256 + t);
    else if (b < 2336) idwt_body<50, 100, 3964928>(yl4, yh4, (b - 1936) * 256 + t);
    else               idwt_body<50, 100, 4784128>(yl5, yh5, (b - 2336) * 256 + t);
}

// ---------------------------------------------------------------------------
// Gather helpers (arithmetic identical to 336us build).
// ---------------------------------------------------------------------------
template <int W2, int OFF, int J, int K>
__device__ __forceinline__ void prep(const float p4[4], int& oenc,
                                     float& wy, float& wx) {
    float y = (p4[J] + 1.0f) * 0.5f * 127.0f;
    float x = (p4[K] + 1.0f) * 0.5f * (float)(W2 - 1);

    float yf = fminf(fmaxf(floorf(y), 0.0f), 127.0f);
    float xf = fminf(fmaxf(floorf(x), 0.0f), (float)(W2 - 1));
    int y0 = (int)yf, x0 = (int)xf;
    int y1 = min(y0 + 1, 127);
    int x1 = min(x0 + 1, W2 - 1);
    wy = fminf(fmaxf(y - yf, 0.0f), 1.0f);
    wx = fminf(fmaxf(x - xf, 0.0f), 1.0f);

    oenc = (OFF + (y0 * W2 + x0) * 64)
         | ((x1 > x0) ? (1 << 24) : 0)
         | ((y1 > y0) ? (1 << 25) : 0);
}

template <int DYC>
__device__ __forceinline__ void samp(int oenc, float wy, float wx,
                                     int lane2, ull& prod) {
    int base = (oenc & 0xFFFFFF) + lane2;
    int dx = ((oenc >> 24) & 1) << 6;
    int dy = (oenc & (1 << 25)) ? DYC : 0;

    float om_y = 1.0f - wy, om_x = 1.0f - wx;
    ull w00 = pack2(om_y * om_x);
    ull w01 = pack2(om_y * wx);
    ull w10 = pack2(wy * om_x);
    ull w11 = pack2(wy * wx);

    const __half* gp = g_planes;
    unsigned v00 = *(const unsigned*)(gp + base);
    unsigned v01 = *(const unsigned*)(gp + base + dx);
    unsigned v10 = *(const unsigned*)(gp + base + dy);
    unsigned v11 = *(const unsigned*)(gp + base + dy + dx);

    ull acc = 0ull;
    ffma2(acc, w00, h2f2(v00));
    ffma2(acc, w01, h2f2(v01));
    ffma2(acc, w10, h2f2(v10));
    ffma2(acc, w11, h2f2(v11));
    mul2(prod, prod, acc);
}

// ---------------------------------------------------------------------------
// Tensor-core MLP pieces (unchanged from 336us build).
// ---------------------------------------------------------------------------
#define XS   70      // X row stride in halves
#define WST  70      // weight row stride in halves (64-wide K)
#define C1ST 38      // Wc1 row stride in halves (32-wide K)
#define XFS  17      // f32 staging row stride in floats

template <int KT, int NT, int WSTRIDE, bool F32OUT>
__device__ __forceinline__ void mma_layer(__half* Xh, const __half* Wt,
                                          float* Xf, int lane) {
    int g = lane >> 2, t = lane & 3;

    unsigned a[2][KT][4];
#pragma unroll
    for (int mt = 0; mt < 2; mt++) {
#pragma unroll
        for (int k = 0; k < KT; k++) {
            int r = mt * 16 + g;
            int c = k * 16 + 2 * t;
            a[mt][k][0] = *(const unsigned*)&Xh[r * XS + c];
            a[mt][k][1] = *(const unsigned*)&Xh[(r + 8) * XS + c];
            a[mt][k][2] = *(const unsigned*)&Xh[r * XS + c + 8];
            a[mt][k][3] = *(const unsigned*)&Xh[(r + 8) * XS + c + 8];
        }
    }
    __syncwarp();

#pragma unroll
    for (int nt = 0; nt < NT; nt++) {
        float cacc[2][4] = {{0.f, 0.f, 0.f, 0.f}, {0.f, 0.f, 0.f, 0.f}};
#pragma unroll
        for (int k = 0; k < KT; k++) {
            const __half* wrow = Wt + (nt * 8 + g) * WSTRIDE + k * 16 + 2 * t;
            unsigned b0 = *(const unsigned*)(wrow);
            unsigned b1 = *(const unsigned*)(wrow + 8);
            mma16816(cacc[0], a[0][k], b0, b1);
            mma16816(cacc[1], a[1][k], b0, b1);
        }
#pragma unroll
        for (int mt = 0; mt < 2; mt++) {
            float v0 = cacc[mt][0], v1 = cacc[mt][1];
            float v2 = cacc[mt][2], v3 = cacc[mt][3];
            int r = mt * 16 + g;
            int c = nt * 8 + 2 * t;
            if (F32OUT) {
                Xf[r * XFS + c]           = v0;
                Xf[r * XFS + c + 1]       = v1;
                Xf[(r + 8) * XFS + c]     = v2;
                Xf[(r + 8) * XFS + c + 1] = v3;
            } else {
                v0 = fmaxf(v0, 0.f); v1 = fmaxf(v1, 0.f);
                v2 = fmaxf(v2, 0.f); v3 = fmaxf(v3, 0.f);
                *(unsigned*)&Xh[r * XS + c]       = packh2(v0, v1);
                *(unsigned*)&Xh[(r + 8) * XS + c] = packh2(v2, v3);
            }
        }
    }
    __syncwarp();
}

// ---------------------------------------------------------------------------
// Fused kernel: gather writes features DIRECTLY into the per-warp fp16 X
// tile, then the tensor-core MLP chain runs on it. No global feature scratch.
// Smem: ~25.8 KB weights + 17.9 KB X tiles = 43.7 KB static.
// ---------------------------------------------------------------------------
__global__ __launch_bounds__(128) void wf_fused(
    const float* __restrict__ pts, const float* __restrict__ ts,
    const float* __restrict__ dirs,
    const float* __restrict__ Wsig1, const float* __restrict__ Wsig2,
    const float* __restrict__ Wc1, const float* __restrict__ Wc2,
    const float* __restrict__ Wc3, float* __restrict__ outp) {

    __shared__ __align__(16) __half sW1t[64 * WST];
    __shared__ __align__(16) __half sW2t[16 * WST];
    __shared__ __align__(16) __half sC1t[64 * C1ST];
    __shared__ __align__(16) __half sC2t[64 * WST];
    __shared__ float sC3[64 * 3];
    __shared__ __align__(16) __half sX[4][32 * XS];

    int tid = threadIdx.x;

    // Weight convert + transpose: W[k][n] f32 -> Wt[n][k] f16.
    for (int idx = tid; idx < 64 * 64; idx += 128) {
        int k = idx >> 6, nn = idx & 63;
        sW1t[nn * WST + k] = __float2half(Wsig1[idx]);
        sC2t[nn * WST + k] = __float2half(Wc2[idx]);
    }
    for (int idx = tid; idx < 64 * 16; idx += 128) {
        int k = idx >> 4, nn = idx & 15;
        sW2t[nn * WST + k] = __float2half(Wsig2[idx]);
    }
    for (int idx = tid; idx < 31 * 64; idx += 128) {
        int k = idx >> 6, nn = idx & 63;
        sC1t[nn * C1ST + k] = __float2half(Wc1[idx]);
    }
    for (int idx = tid; idx < 64; idx += 128) {
        sC1t[idx * C1ST + 31] = __float2half(0.0f);
    }
    for (int idx = tid; idx < 64 * 3; idx += 128) sC3[idx] = Wc3[idx];
    __syncthreads();

    int lane = tid & 31;
    int warp = tid >> 5;
    int n = blockIdx.x * 128 + tid;   // this lane's sample

    __half* Xh = sX[warp];
    float*  Xf = (float*)Xh;

    // ================= GATHER PHASE =================
    {
        float p4[4];
        p4[0] = pts[3*n + 0];
        p4[1] = pts[3*n + 1];
        p4[2] = pts[3*n + 2];
        p4[3] = ts[n >> 6] * 2.0f - 1.0f;

        int   oe0, oe1, oe2, oe3, oe4, oe5;
        float wy0, wy1, wy2, wy3, wy4, wy5;
        float wx0, wx1, wx2, wx3, wx4, wx5;
        prep<128,       0, 0, 1>(p4, oe0, wy0, wx0);
        prep<128, 1048576, 0, 2>(p4, oe1, wy1, wx1);
        prep<100, 2097152, 0, 3>(p4, oe2, wy2, wx2);
        prep<128, 2916352, 1, 2>(p4, oe3, wy3, wx3);
        prep<100, 3964928, 1, 3>(p4, oe4, wy4, wx4);
        prep<100, 4784128, 2, 3>(p4, oe5, wy5, wx5);

        int lane2 = 2 * lane;

#pragma unroll 1
        for (int s = 0; s < 32; s++) {
            ull prod = pack2(1.0f);

#define DO_COMBO(OE, WY, WX, DYC)                                  \
            {                                                      \
                int   o  = __shfl_sync(0xffffffffu, OE, s);        \
                float a_ = __shfl_sync(0xffffffffu, WY, s);        \
                float b_ = __shfl_sync(0xffffffffu, WX, s);        \
                samp<DYC>(o, a_, b_, lane2, prod);                 \
            }
            DO_COMBO(oe0, wy0, wx0, 8192)
            DO_COMBO(oe1, wy1, wx1, 8192)
            DO_COMBO(oe2, wy2, wx2, 6400)
            DO_COMBO(oe3, wy3, wx3, 8192)
            DO_COMBO(oe4, wy4, wx4, 6400)
            DO_COMBO(oe5, wy5, wx5, 6400)
#undef DO_COMBO

            float fh, fl;
            unpack2(prod, fh, fl);
            // Direct into X tile: row = sample s, cols = lane (hi), 32+lane (lo)
            Xh[s * XS + lane]      = __float2half_rn(fh);
            Xh[s * XS + 32 + lane] = __float2half_rn(fl);
        }
        __syncwarp();
    }

    // ================= MLP PHASE (tensor cores) =================

    // ---- Layer 1: 64 -> 64, relu ----
    mma_layer<4, 8, WST, false>(Xh, sW1t, Xf, lane);

    // ---- Layer 2: 64 -> 16, no relu, fp32 out ----
    mma_layer<4, 2, WST, true>(Xh, sW2t, Xf, lane);

    // ---- Per-lane: density + SH + geo -> ci fp16 ----
    float ov[16];
#pragma unroll
    for (int j = 0; j < 16; j++) ov[j] = Xf[lane * XFS + j];
    float density = expf(fminf(fmaxf(ov[15], -15.0f), 15.0f));

    int r = n >> 6;
    float dxv = dirs[3*r + 0], dyv = dirs[3*r + 1], dzv = dirs[3*r + 2];
    float inv = rsqrtf(dxv*dxv + dyv*dyv + dzv*dzv);
    float X = dxv * inv, Y = dyv * inv, Z = dzv * inv;
    float xx = X * X, yy = Y * Y, zz = Z * Z;

    float ci[32];
    ci[0]  = 0.28209479177387814f;
    ci[1]  = -0.4886025119029199f * Y;
    ci[2]  = 0.4886025119029199f * Z;
    ci[3]  = -0.4886025119029199f * X;
    ci[4]  = 1.0925484305920792f * X * Y;
    ci[5]  = -1.0925484305920792f * Y * Z;
    ci[6]  = 0.31539156525252005f * (3.0f * zz - 1.0f);
    ci[7]  = -1.0925484305920792f * X * Z;
    ci[8]  = 0.5462742152960396f * (xx - yy);
    ci[9]  = -0.5900435899266435f * Y * (3.0f * xx - yy);
    ci[10] = 2.890611442640554f * X * Y * Z;
    ci[11] = -0.4570457994644658f * Y * (5.0f * zz - 1.0f);
    ci[12] = 0.3731763325901154f * Z * (5.0f * zz - 3.0f);
    ci[13] = -0.4570457994644658f * X * (5.0f * zz - 1.0f);
    ci[14] = 1.445305721320277f * Z * (xx - yy);
    ci[15] = -0.5900435899266435f * X * (xx - 3.0f * yy);
#pragma unroll
    for (int g2 = 0; g2 < 15; g2++) ci[16 + g2] = ov[g2];
    ci[31] = 0.0f;

    __syncwarp();   // all lanes done reading Xf before overwriting as fp16
#pragma unroll
    for (int q = 0; q < 16; q++) {
        *(unsigned*)&Xh[lane * XS + 2 * q] = packh2(ci[2*q], ci[2*q + 1]);
    }
    __syncwarp();

    // ---- Layer C1: 32(31+pad) -> 64, relu ----
    mma_layer<2, 8, C1ST, false>(Xh, sC1t, Xf, lane);

    // ---- Layer C2: 64 -> 64, relu ----
    mma_layer<4, 8, WST, false>(Xh, sC2t, Xf, lane);

    // ---- Layer C3 (SIMT): 64 -> 3, sigmoid ----
    float r0 = 0.f, r1 = 0.f, r2 = 0.f;
#pragma unroll
    for (int q = 0; q < 32; q++) {
        float f0, f1;
        unph2(*(const unsigned*)&Xh[lane * XS + 2 * q], f0, f1);
        const float* w0 = sC3 + (2*q) * 3;
        const float* w1 = sC3 + (2*q + 1) * 3;
        r0 += f0 * w0[0] + f1 * w1[0];
        r1 += f0 * w0[1] + f1 * w1[1];
        r2 += f0 * w0[2] + f1 * w1[2];
    }

    float4 res;
    res.x = 1.0f / (1.0f + expf(-r0));
    res.y = 1.0f / (1.0f + expf(-r1));
    res.z = 1.0f / (1.0f + expf(-r2));
    res.w = density;
    *(float4*)(outp + 4 * n) = res;
}

// ---------------------------------------------------------------------------
// Launch
// ---------------------------------------------------------------------------
extern "C" void kernel_launch(void* const* d_in, const int* in_sizes, int n_in,
                              void* d_out, int out_size) {
    const float* pts  = (const float*)d_in[0];
    const float* dirs = (const float*)d_in[1];
    const float* ts   = (const float*)d_in[2];
    const float* yl0 = (const float*)d_in[3];  const float* yh0 = (const float*)d_in[4];
    const float* yl1 = (const float*)d_in[5];  const float* yh1 = (const float*)d_in[6];
    const float* yl2 = (const float*)d_in[7];  const float* yh2 = (const float*)d_in[8];
    const float* yl3 = (const float*)d_in[9];  const float* yh3 = (const float*)d_in[10];
    const float* yl4 = (const float*)d_in[11]; const float* yh4 = (const float*)d_in[12];
    const float* yl5 = (const float*)d_in[13]; const float* yh5 = (const float*)d_in[14];
    const float* Wsig1 = (const float*)d_in[15];
    const float* Wsig2 = (const float*)d_in[16];
    const float* Wc1   = (const float*)d_in[17];
    const float* Wc2   = (const float*)d_in[18];
    const float* Wc3   = (const float*)d_in[19];

    wf_nop<<<1, 32>>>();   // keeps ncu sampled slot on wf_fused

    idwt_all<<<2736, 256>>>(yl0, yh0, yl1, yh1, yl2, yh2,
                            yl3, yh3, yl4, yh4, yl5, yh5);

    wf_fused<<<NSAMP / 128, 128>>>(pts, ts, dirs,
                                   Wsig1, Wsig2, Wc1, Wc2, Wc3,
                                   (float*)d_out);
}

// round 16
// speedup vs baseline: 3.0459x; 1.0826x over previous
#include <cuda_runtime.h>
#include <cuda_fp16.h>
#include <math.h>

// ---------------------------------------------------------------------------
// Problem constants
// ---------------------------------------------------------------------------
#define NSAMP    524288      // 8192 rays * 64 samples

// combos: (0,1) (0,2) (0,3) (1,2) (1,3) (2,3)
// widths: 64,64,50,64,50,50  ->  W2: 128,128,100,128,100,100
// Interleaved plane-pair layout per combo: [Y][X][C=32][2] = (hi, lo), fp16.
#define TOTAL_PLANE_ELEMS 5603328   // halves: 11.2 MB

__device__ __half g_planes[TOTAL_PLANE_ELEMS];

typedef unsigned long long ull;

// ---------------------------------------------------------------------------
// half2 helpers
// ---------------------------------------------------------------------------
__device__ __forceinline__ void unph2(unsigned v, float& f0, float& f1) {
    __half2 h = *(__half2*)&v;
    float2 f = __half22float2(h);
    f0 = f.x; f1 = f.y;
}
__device__ __forceinline__ unsigned packh2(float f0, float f1) {
    __half2 h = __floats2half2_rn(f0, f1);
    return *(unsigned*)&h;
}

// m16n8k16 fp16 MMA, fp32 accumulate (HMMA).
__device__ __forceinline__ void mma16816(float c[4], const unsigned a[4],
                                         unsigned b0, unsigned b1) {
    asm volatile(
        "mma.sync.aligned.m16n8k16.row.col.f32.f16.f16.f32 "
        "{%0,%1,%2,%3}, {%4,%5,%6,%7}, {%8,%9}, {%0,%1,%2,%3};"
        : "+f"(c[0]), "+f"(c[1]), "+f"(c[2]), "+f"(c[3])
        : "r"(a[0]), "r"(a[1]), "r"(a[2]), "r"(a[3]), "r"(b0), "r"(b1));
}

// ---------------------------------------------------------------------------
// IDWT precompute (unchanged).
// ---------------------------------------------------------------------------
template <int W, int W2, int OFF>
__device__ __forceinline__ void idwt_body(const float* __restrict__ yl,
                                          const float* __restrict__ yh,
                                          int idx) {
    if (idx >= 32 * 64 * W) return;

    int j0   = idx % W;
    int rest = idx / W;
    int i0   = rest & 63;
    int c    = rest >> 6;

    float a  = yl[(c * 64 + i0) * W + j0];
    float lh = yh[((c * 3 + 0) * 64 + i0) * W + j0];
    float hl = yh[((c * 3 + 1) * 64 + i0) * W + j0];
    float hh = yh[((c * 3 + 2) * 64 + i0) * W + j0];

    float ee = 0.5f * (a + lh + hl + hh);
    float eo = 0.5f * (a + lh - hl - hh);
    float oe = 0.5f * (a - lh + hl - hh);
    float oo = 0.5f * (a - lh - hl + hh);
    float lo = 0.5f * a;

    int fi = OFF + ((2 * i0) * W2 + 2 * j0) * 64 + 2 * c;
    __half* gp = g_planes;
    *(__half2*)(gp + fi)                = __floats2half2_rn(ee, lo);
    *(__half2*)(gp + fi + 64)           = __floats2half2_rn(eo, lo);
    *(__half2*)(gp + fi + W2 * 64)      = __floats2half2_rn(oe, lo);
    *(__half2*)(gp + fi + W2 * 64 + 64) = __floats2half2_rn(oo, lo);
}

__global__ __launch_bounds__(256) void idwt_all(
    const float* __restrict__ yl0, const float* __restrict__ yh0,
    const float* __restrict__ yl1, const float* __restrict__ yh1,
    const float* __restrict__ yl2, const float* __restrict__ yh2,
    const float* __restrict__ yl3, const float* __restrict__ yh3,
    const float* __restrict__ yl4, const float* __restrict__ yh4,
    const float* __restrict__ yl5, const float* __restrict__ yh5) {
    int b = blockIdx.x;
    int t = threadIdx.x;
    if      (b <  512) idwt_body<64, 128,       0>(yl0, yh0, (b       ) * 256 + t);
    else if (b < 1024) idwt_body<64, 128, 1048576>(yl1, yh1, (b -  512) * 256 + t);
    else if (b < 1424) idwt_body<50, 100, 2097152>(yl2, yh2, (b - 1024) * 256 + t);
    else if (b < 1936) idwt_body<64, 128, 2916352>(yl3, yh3, (b - 1424) * 256 + t);
    else if (b < 2336) idwt_body<50, 100, 3964928>(yl4, yh4, (b - 1936) * 256 + t);
    else               idwt_body<50, 100, 4784128>(yl5, yh5, (b - 2336) * 256 + t);
}

// ---------------------------------------------------------------------------
// Gather helpers.
// prep: per-sample coordinate math + packed fp16 bilerp weights.
// Offset encoding: bits[0:24) = OFF + (y0*W2+x0)*64 (element units),
//                  bit 24 = (x1>x0), bit 25 = (y1>y0).
// wA = (w00, w01) half2, wB = (w10, w11) half2.
// ---------------------------------------------------------------------------
template <int W2, int OFF, int J, int K>
__device__ __forceinline__ void prep(const float p4[4], int& oenc,
                                     unsigned& wA, unsigned& wB) {
    float y = (p4[J] + 1.0f) * 0.5f * 127.0f;
    float x = (p4[K] + 1.0f) * 0.5f * (float)(W2 - 1);

    float yf = fminf(fmaxf(floorf(y), 0.0f), 127.0f);
    float xf = fminf(fmaxf(floorf(x), 0.0f), (float)(W2 - 1));
    int y0 = (int)yf, x0 = (int)xf;
    int y1 = min(y0 + 1, 127);
    int x1 = min(x0 + 1, W2 - 1);
    float wy = fminf(fmaxf(y - yf, 0.0f), 1.0f);
    float wx = fminf(fmaxf(x - xf, 0.0f), 1.0f);

    oenc = (OFF + (y0 * W2 + x0) * 64)
         | ((x1 > x0) ? (1 << 24) : 0)
         | ((y1 > y0) ? (1 << 25) : 0);

    float om_y = 1.0f - wy, om_x = 1.0f - wx;
    wA = packh2(om_y * om_x, om_y * wx);
    wB = packh2(wy * om_x,   wy * wx);
}

// In-loop sampling: 4 half2 corner loads + fp16 bilerp + product.
template <int DYC>   // DYC = W2*64 (element units)
__device__ __forceinline__ void samp(int oenc, unsigned wAu, unsigned wBu,
                                     int lane2, __half2& prod) {
    int base = (oenc & 0xFFFFFF) + lane2;
    int dx = ((oenc >> 24) & 1) << 6;
    int dy = (oenc & (1 << 25)) ? DYC : 0;

    const __half* gp = g_planes;
    __half2 c00 = *(const __half2*)(gp + base);
    __half2 c01 = *(const __half2*)(gp + base + dx);
    __half2 c10 = *(const __half2*)(gp + base + dy);
    __half2 c11 = *(const __half2*)(gp + base + dy + dx);

    __half2 wA = *(__half2*)&wAu;
    __half2 wB = *(__half2*)&wBu;

    __half2 acc = __hmul2(__low2half2(wA), c00);
    acc = __hfma2(__high2half2(wA), c01, acc);
    acc = __hfma2(__low2half2(wB), c10, acc);
    acc = __hfma2(__high2half2(wB), c11, acc);
    prod = __hmul2(prod, acc);
}

// ---------------------------------------------------------------------------
// Tensor-core MLP pieces (unchanged from 242us build).
// ---------------------------------------------------------------------------
#define XS   70      // X row stride in halves
#define WST  70      // weight row stride in halves (64-wide K)
#define C1ST 38      // Wc1 row stride in halves (32-wide K)
#define XFS  17      // f32 staging row stride in floats

template <int KT, int NT, int WSTRIDE, bool F32OUT>
__device__ __forceinline__ void mma_layer(__half* Xh, const __half* Wt,
                                          float* Xf, int lane) {
    int g = lane >> 2, t = lane & 3;

    unsigned a[2][KT][4];
#pragma unroll
    for (int mt = 0; mt < 2; mt++) {
#pragma unroll
        for (int k = 0; k < KT; k++) {
            int r = mt * 16 + g;
            int c = k * 16 + 2 * t;
            a[mt][k][0] = *(const unsigned*)&Xh[r * XS + c];
            a[mt][k][1] = *(const unsigned*)&Xh[(r + 8) * XS + c];
            a[mt][k][2] = *(const unsigned*)&Xh[r * XS + c + 8];
            a[mt][k][3] = *(const unsigned*)&Xh[(r + 8) * XS + c + 8];
        }
    }
    __syncwarp();

#pragma unroll
    for (int nt = 0; nt < NT; nt++) {
        float cacc[2][4] = {{0.f, 0.f, 0.f, 0.f}, {0.f, 0.f, 0.f, 0.f}};
#pragma unroll
        for (int k = 0; k < KT; k++) {
            const __half* wrow = Wt + (nt * 8 + g) * WSTRIDE + k * 16 + 2 * t;
            unsigned b0 = *(const unsigned*)(wrow);
            unsigned b1 = *(const unsigned*)(wrow + 8);
            mma16816(cacc[0], a[0][k], b0, b1);
            mma16816(cacc[1], a[1][k], b0, b1);
        }
#pragma unroll
        for (int mt = 0; mt < 2; mt++) {
            float v0 = cacc[mt][0], v1 = cacc[mt][1];
            float v2 = cacc[mt][2], v3 = cacc[mt][3];
            int r = mt * 16 + g;
            int c = nt * 8 + 2 * t;
            if (F32OUT) {
                Xf[r * XFS + c]           = v0;
                Xf[r * XFS + c + 1]       = v1;
                Xf[(r + 8) * XFS + c]     = v2;
                Xf[(r + 8) * XFS + c + 1] = v3;
            } else {
                v0 = fmaxf(v0, 0.f); v1 = fmaxf(v1, 0.f);
                v2 = fmaxf(v2, 0.f); v3 = fmaxf(v3, 0.f);
                *(unsigned*)&Xh[r * XS + c]       = packh2(v0, v1);
                *(unsigned*)&Xh[(r + 8) * XS + c] = packh2(v2, v3);
            }
        }
    }
    __syncwarp();
}

// ---------------------------------------------------------------------------
// Fused kernel: gather writes features DIRECTLY into the per-warp fp16 X
// tile, then the tensor-core MLP chain runs on it.
// ---------------------------------------------------------------------------
__global__ __launch_bounds__(128) void wf_fused(
    const float* __restrict__ pts, const float* __restrict__ ts,
    const float* __restrict__ dirs,
    const float* __restrict__ Wsig1, const float* __restrict__ Wsig2,
    const float* __restrict__ Wc1, const float* __restrict__ Wc2,
    const float* __restrict__ Wc3, float* __restrict__ outp) {

    __shared__ __align__(16) __half sW1t[64 * WST];
    __shared__ __align__(16) __half sW2t[16 * WST];
    __shared__ __align__(16) __half sC1t[64 * C1ST];
    __shared__ __align__(16) __half sC2t[64 * WST];
    __shared__ float sC3[64 * 3];
    __shared__ __align__(16) __half sX[4][32 * XS];

    int tid = threadIdx.x;

    // Weight convert + transpose: W[k][n] f32 -> Wt[n][k] f16.
    for (int idx = tid; idx < 64 * 64; idx += 128) {
        int k = idx >> 6, nn = idx & 63;
        sW1t[nn * WST + k] = __float2half(Wsig1[idx]);
        sC2t[nn * WST + k] = __float2half(Wc2[idx]);
    }
    for (int idx = tid; idx < 64 * 16; idx += 128) {
        int k = idx >> 4, nn = idx & 15;
        sW2t[nn * WST + k] = __float2half(Wsig2[idx]);
    }
    for (int idx = tid; idx < 31 * 64; idx += 128) {
        int k = idx >> 6, nn = idx & 63;
        sC1t[nn * C1ST + k] = __float2half(Wc1[idx]);
    }
    for (int idx = tid; idx < 64; idx += 128) {
        sC1t[idx * C1ST + 31] = __float2half(0.0f);
    }
    for (int idx = tid; idx < 64 * 3; idx += 128) sC3[idx] = Wc3[idx];
    __syncthreads();

    int lane = tid & 31;
    int warp = tid >> 5;
    int n = blockIdx.x * 128 + tid;   // this lane's sample

    __half* Xh = sX[warp];
    float*  Xf = (float*)Xh;

    // ================= GATHER PHASE =================
    {
        float p4[4];
        p4[0] = pts[3*n + 0];
        p4[1] = pts[3*n + 1];
        p4[2] = pts[3*n + 2];
        p4[3] = ts[n >> 6] * 2.0f - 1.0f;

        int      oe0, oe1, oe2, oe3, oe4, oe5;
        unsigned a0, a1, a2, a3, a4, a5;
        unsigned b0, b1, b2, b3, b4, b5;
        prep<128,       0, 0, 1>(p4, oe0, a0, b0);
        prep<128, 1048576, 0, 2>(p4, oe1, a1, b1);
        prep<100, 2097152, 0, 3>(p4, oe2, a2, b2);
        prep<128, 2916352, 1, 2>(p4, oe3, a3, b3);
        prep<100, 3964928, 1, 3>(p4, oe4, a4, b4);
        prep<100, 4784128, 2, 3>(p4, oe5, a5, b5);

        int lane2 = 2 * lane;

#pragma unroll 1
        for (int s = 0; s < 32; s++) {
            __half2 prod = __floats2half2_rn(1.0f, 1.0f);

#define DO_COMBO(OE, WA, WB, DYC)                                  \
            {                                                      \
                int      o  = __shfl_sync(0xffffffffu, OE, s);     \
                unsigned u_ = __shfl_sync(0xffffffffu, WA, s);     \
                unsigned v_ = __shfl_sync(0xffffffffu, WB, s);     \
                samp<DYC>(o, u_, v_, lane2, prod);                 \
            }
            DO_COMBO(oe0, a0, b0, 8192)
            DO_COMBO(oe1, a1, b1, 8192)
            DO_COMBO(oe2, a2, b2, 6400)
            DO_COMBO(oe3, a3, b3, 8192)
            DO_COMBO(oe4, a4, b4, 6400)
            DO_COMBO(oe5, a5, b5, 6400)
#undef DO_COMBO

            // Direct into X tile: row = sample s, cols = lane (hi), 32+lane (lo)
            Xh[s * XS + lane]      = __low2half(prod);
            Xh[s * XS + 32 + lane] = __high2half(prod);
        }
        __syncwarp();
    }

    // ================= MLP PHASE (tensor cores) =================

    // ---- Layer 1: 64 -> 64, relu ----
    mma_layer<4, 8, WST, false>(Xh, sW1t, Xf, lane);

    // ---- Layer 2: 64 -> 16, no relu, fp32 out ----
    mma_layer<4, 2, WST, true>(Xh, sW2t, Xf, lane);

    // ---- Per-lane: density + SH + geo -> ci fp16 ----
    float ov[16];
#pragma unroll
    for (int j = 0; j < 16; j++) ov[j] = Xf[lane * XFS + j];
    float density = expf(fminf(fmaxf(ov[15], -15.0f), 15.0f));

    int r = n >> 6;
    float dxv = dirs[3*r + 0], dyv = dirs[3*r + 1], dzv = dirs[3*r + 2];
    float inv = rsqrtf(dxv*dxv + dyv*dyv + dzv*dzv);
    float X = dxv * inv, Y = dyv * inv, Z = dzv * inv;
    float xx = X * X, yy = Y * Y, zz = Z * Z;

    float ci[32];
    ci[0]  = 0.28209479177387814f;
    ci[1]  = -0.4886025119029199f * Y;
    ci[2]  = 0.4886025119029199f * Z;
    ci[3]  = -0.4886025119029199f * X;
    ci[4]  = 1.0925484305920792f * X * Y;
    ci[5]  = -1.0925484305920792f * Y * Z;
    ci[6]  = 0.31539156525252005f * (3.0f * zz - 1.0f);
    ci[7]  = -1.0925484305920792f * X * Z;
    ci[8]  = 0.5462742152960396f * (xx - yy);
    ci[9]  = -0.5900435899266435f * Y * (3.0f * xx - yy);
    ci[10] = 2.890611442640554f * X * Y * Z;
    ci[11] = -0.4570457994644658f * Y * (5.0f * zz - 1.0f);
    ci[12] = 0.3731763325901154f * Z * (5.0f * zz - 3.0f);
    ci[13] = -0.4570457994644658f * X * (5.0f * zz - 1.0f);
    ci[14] = 1.445305721320277f * Z * (xx - yy);
    ci[15] = -0.5900435899266435f * X * (xx - 3.0f * yy);
#pragma unroll
    for (int g2 = 0; g2 < 15; g2++) ci[16 + g2] = ov[g2];
    ci[31] = 0.0f;

    __syncwarp();   // all lanes done reading Xf before overwriting as fp16
#pragma unroll
    for (int q = 0; q < 16; q++) {
        *(unsigned*)&Xh[lane * XS + 2 * q] = packh2(ci[2*q], ci[2*q + 1]);
    }
    __syncwarp();

    // ---- Layer C1: 32(31+pad) -> 64, relu ----
    mma_layer<2, 8, C1ST, false>(Xh, sC1t, Xf, lane);

    // ---- Layer C2: 64 -> 64, relu ----
    mma_layer<4, 8, WST, false>(Xh, sC2t, Xf, lane);

    // ---- Layer C3 (SIMT): 64 -> 3, sigmoid ----
    float r0 = 0.f, r1 = 0.f, r2 = 0.f;
#pragma unroll
    for (int q = 0; q < 32; q++) {
        float f0, f1;
        unph2(*(const unsigned*)&Xh[lane * XS + 2 * q], f0, f1);
        const float* w0 = sC3 + (2*q) * 3;
        const float* w1 = sC3 + (2*q + 1) * 3;
        r0 += f0 * w0[0] + f1 * w1[0];
        r1 += f0 * w0[1] + f1 * w1[1];
        r2 += f0 * w0[2] + f1 * w1[2];
    }

    float4 res;
    res.x = 1.0f / (1.0f + expf(-r0));
    res.y = 1.0f / (1.0f + expf(-r1));
    res.z = 1.0f / (1.0f + expf(-r2));
    res.w = density;
    *(float4*)(outp + 4 * n) = res;
}

// ---------------------------------------------------------------------------
// Launch
// ---------------------------------------------------------------------------
extern "C" void kernel_launch(void* const* d_in, const int* in_sizes, int n_in,
                              void* d_out, int out_size) {
    const float* pts  = (const float*)d_in[0];
    const float* dirs = (const float*)d_in[1];
    const float* ts   = (const float*)d_in[2];
    const float* yl0 = (const float*)d_in[3];  const float* yh0 = (const float*)d_in[4];
    const float* yl1 = (const float*)d_in[5];  const float* yh1 = (const float*)d_in[6];
    const float* yl2 = (const float*)d_in[7];  const float* yh2 = (const float*)d_in[8];
    const float* yl3 = (const float*)d_in[9];  const float* yh3 = (const float*)d_in[10];
    const float* yl4 = (const float*)d_in[11]; const float* yh4 = (const float*)d_in[12];
    const float* yl5 = (const float*)d_in[13]; const float* yh5 = (const float*)d_in[14];
    const float* Wsig1 = (const float*)d_in[15];
    const float* Wsig2 = (const float*)d_in[16];
    const float* Wc1   = (const float*)d_in[17];
    const float* Wc2   = (const float*)d_in[18];
    const float* Wc3   = (const float*)d_in[19];

    idwt_all<<<2736, 256>>>(yl0, yh0, yl1, yh1, yl2, yh2,
                            yl3, yh3, yl4, yh4, yl5, yh5);

    wf_fused<<<NSAMP / 128, 128>>>(pts, ts, dirs,
                                   Wsig1, Wsig2, Wc1, Wc2, Wc3,
                                   (float*)d_out);
}

// round 17
// speedup vs baseline: 3.1178x; 1.0236x over previous
#include <cuda_runtime.h>
#include <cuda_fp16.h>
#include <math.h>

// ---------------------------------------------------------------------------
// Problem constants
// ---------------------------------------------------------------------------
#define NSAMP    524288      // 8192 rays * 64 samples

// combos: (0,1) (0,2) (0,3) (1,2) (1,3) (2,3)
// widths: 64,64,50,64,50,50  ->  W2: 128,128,100,128,100,100
// Interleaved plane-pair layout per combo: [Y][X][C=32][2] = (hi, lo), fp16.
#define TOTAL_PLANE_ELEMS 5603328   // halves: 11.2 MB

__device__ __half g_planes[TOTAL_PLANE_ELEMS];

typedef unsigned long long ull;

// ---------------------------------------------------------------------------
// half2 helpers
// ---------------------------------------------------------------------------
__device__ __forceinline__ void unph2(unsigned v, float& f0, float& f1) {
    __half2 h = *(__half2*)&v;
    float2 f = __half22float2(h);
    f0 = f.x; f1 = f.y;
}
__device__ __forceinline__ unsigned packh2(float f0, float f1) {
    __half2 h = __floats2half2_rn(f0, f1);
    return *(unsigned*)&h;
}

// m16n8k16 fp16 MMA, fp32 accumulate (HMMA).
__device__ __forceinline__ void mma16816(float c[4], const unsigned a[4],
                                         unsigned b0, unsigned b1) {
    asm volatile(
        "mma.sync.aligned.m16n8k16.row.col.f32.f16.f16.f32 "
        "{%0,%1,%2,%3}, {%4,%5,%6,%7}, {%8,%9}, {%0,%1,%2,%3};"
        : "+f"(c[0]), "+f"(c[1]), "+f"(c[2]), "+f"(c[3])
        : "r"(a[0]), "r"(a[1]), "r"(a[2]), "r"(a[3]), "r"(b0), "r"(b1));
}

// ---------------------------------------------------------------------------
// IDWT precompute (unchanged).
// ---------------------------------------------------------------------------
template <int W, int W2, int OFF>
__device__ __forceinline__ void idwt_body(const float* __restrict__ yl,
                                          const float* __restrict__ yh,
                                          int idx) {
    if (idx >= 32 * 64 * W) return;

    int j0   = idx % W;
    int rest = idx / W;
    int i0   = rest & 63;
    int c    = rest >> 6;

    float a  = yl[(c * 64 + i0) * W + j0];
    float lh = yh[((c * 3 + 0) * 64 + i0) * W + j0];
    float hl = yh[((c * 3 + 1) * 64 + i0) * W + j0];
    float hh = yh[((c * 3 + 2) * 64 + i0) * W + j0];

    float ee = 0.5f * (a + lh + hl + hh);
    float eo = 0.5f * (a + lh - hl - hh);
    float oe = 0.5f * (a - lh + hl - hh);
    float oo = 0.5f * (a - lh - hl + hh);
    float lo = 0.5f * a;

    int fi = OFF + ((2 * i0) * W2 + 2 * j0) * 64 + 2 * c;
    __half* gp = g_planes;
    *(__half2*)(gp + fi)                = __floats2half2_rn(ee, lo);
    *(__half2*)(gp + fi + 64)           = __floats2half2_rn(eo, lo);
    *(__half2*)(gp + fi + W2 * 64)      = __floats2half2_rn(oe, lo);
    *(__half2*)(gp + fi + W2 * 64 + 64) = __floats2half2_rn(oo, lo);
}

__global__ __launch_bounds__(256) void idwt_all(
    const float* __restrict__ yl0, const float* __restrict__ yh0,
    const float* __restrict__ yl1, const float* __restrict__ yh1,
    const float* __restrict__ yl2, const float* __restrict__ yh2,
    const float* __restrict__ yl3, const float* __restrict__ yh3,
    const float* __restrict__ yl4, const float* __restrict__ yh4,
    const float* __restrict__ yl5, const float* __restrict__ yh5) {
    int b = blockIdx.x;
    int t = threadIdx.x;
    if      (b <  512) idwt_body<64, 128,       0>(yl0, yh0, (b       ) * 256 + t);
    else if (b < 1024) idwt_body<64, 128, 1048576>(yl1, yh1, (b -  512) * 256 + t);
    else if (b < 1424) idwt_body<50, 100, 2097152>(yl2, yh2, (b - 1024) * 256 + t);
    else if (b < 1936) idwt_body<64, 128, 2916352>(yl3, yh3, (b - 1424) * 256 + t);
    else if (b < 2336) idwt_body<50, 100, 3964928>(yl4, yh4, (b - 1936) * 256 + t);
    else               idwt_body<50, 100, 4784128>(yl5, yh5, (b - 2336) * 256 + t);
}

// ---------------------------------------------------------------------------
// Gather helpers (unchanged arithmetic).
// ---------------------------------------------------------------------------
template <int W2, int OFF, int J, int K>
__device__ __forceinline__ void prep(const float p4[4], int& oenc,
                                     unsigned& wA, unsigned& wB) {
    float y = (p4[J] + 1.0f) * 0.5f * 127.0f;
    float x = (p4[K] + 1.0f) * 0.5f * (float)(W2 - 1);

    float yf = fminf(fmaxf(floorf(y), 0.0f), 127.0f);
    float xf = fminf(fmaxf(floorf(x), 0.0f), (float)(W2 - 1));
    int y0 = (int)yf, x0 = (int)xf;
    int y1 = min(y0 + 1, 127);
    int x1 = min(x0 + 1, W2 - 1);
    float wy = fminf(fmaxf(y - yf, 0.0f), 1.0f);
    float wx = fminf(fmaxf(x - xf, 0.0f), 1.0f);

    oenc = (OFF + (y0 * W2 + x0) * 64)
         | ((x1 > x0) ? (1 << 24) : 0)
         | ((y1 > y0) ? (1 << 25) : 0);

    float om_y = 1.0f - wy, om_x = 1.0f - wx;
    wA = packh2(om_y * om_x, om_y * wx);
    wB = packh2(wy * om_x,   wy * wx);
}

template <int DYC>   // DYC = W2*64 (element units)
__device__ __forceinline__ void samp(int oenc, unsigned wAu, unsigned wBu,
                                     int lane2, __half2& prod) {
    int base = (oenc & 0xFFFFFF) + lane2;
    int dx = ((oenc >> 24) & 1) << 6;
    int dy = (oenc & (1 << 25)) ? DYC : 0;

    const __half* gp = g_planes;
    __half2 c00 = *(const __half2*)(gp + base);
    __half2 c01 = *(const __half2*)(gp + base + dx);
    __half2 c10 = *(const __half2*)(gp + base + dy);
    __half2 c11 = *(const __half2*)(gp + base + dy + dx);

    __half2 wA = *(__half2*)&wAu;
    __half2 wB = *(__half2*)&wBu;

    __half2 acc = __hmul2(__low2half2(wA), c00);
    acc = __hfma2(__high2half2(wA), c01, acc);
    acc = __hfma2(__low2half2(wB), c10, acc);
    acc = __hfma2(__high2half2(wB), c11, acc);
    prod = __hmul2(prod, acc);
}

// ---------------------------------------------------------------------------
// Tensor-core MLP pieces (unchanged).
// ---------------------------------------------------------------------------
#define XS   70      // X row stride in halves
#define WST  70      // weight row stride in halves (64-wide K)
#define C1ST 38      // Wc1 row stride in halves (32-wide K)
#define XFS  17      // f32 staging row stride in floats
#define XTILE (32 * XS)   // halves per warp tile

template <int KT, int NT, int WSTRIDE, bool F32OUT>
__device__ __forceinline__ void mma_layer(__half* Xh, const __half* Wt,
                                          float* Xf, int lane) {
    int g = lane >> 2, t = lane & 3;

    unsigned a[2][KT][4];
#pragma unroll
    for (int mt = 0; mt < 2; mt++) {
#pragma unroll
        for (int k = 0; k < KT; k++) {
            int r = mt * 16 + g;
            int c = k * 16 + 2 * t;
            a[mt][k][0] = *(const unsigned*)&Xh[r * XS + c];
            a[mt][k][1] = *(const unsigned*)&Xh[(r + 8) * XS + c];
            a[mt][k][2] = *(const unsigned*)&Xh[r * XS + c + 8];
            a[mt][k][3] = *(const unsigned*)&Xh[(r + 8) * XS + c + 8];
        }
    }
    __syncwarp();

#pragma unroll
    for (int nt = 0; nt < NT; nt++) {
        float cacc[2][4] = {{0.f, 0.f, 0.f, 0.f}, {0.f, 0.f, 0.f, 0.f}};
#pragma unroll
        for (int k = 0; k < KT; k++) {
            const __half* wrow = Wt + (nt * 8 + g) * WSTRIDE + k * 16 + 2 * t;
            unsigned b0 = *(const unsigned*)(wrow);
            unsigned b1 = *(const unsigned*)(wrow + 8);
            mma16816(cacc[0], a[0][k], b0, b1);
            mma16816(cacc[1], a[1][k], b0, b1);
        }
#pragma unroll
        for (int mt = 0; mt < 2; mt++) {
            float v0 = cacc[mt][0], v1 = cacc[mt][1];
            float v2 = cacc[mt][2], v3 = cacc[mt][3];
            int r = mt * 16 + g;
            int c = nt * 8 + 2 * t;
            if (F32OUT) {
                Xf[r * XFS + c]           = v0;
                Xf[r * XFS + c + 1]       = v1;
                Xf[(r + 8) * XFS + c]     = v2;
                Xf[(r + 8) * XFS + c + 1] = v3;
            } else {
                v0 = fmaxf(v0, 0.f); v1 = fmaxf(v1, 0.f);
                v2 = fmaxf(v2, 0.f); v3 = fmaxf(v3, 0.f);
                *(unsigned*)&Xh[r * XS + c]       = packh2(v0, v1);
                *(unsigned*)&Xh[(r + 8) * XS + c] = packh2(v2, v3);
            }
        }
    }
    __syncwarp();
}

// ---------------------------------------------------------------------------
// Fused kernel, 256 threads/block: 8 warps share one weight copy.
// Static smem: weights (~25.8 KB). Dynamic smem: 8 X tiles (35 KB).
// ---------------------------------------------------------------------------
__global__ __launch_bounds__(256) void wf_fused(
    const float* __restrict__ pts, const float* __restrict__ ts,
    const float* __restrict__ dirs,
    const float* __restrict__ Wsig1, const float* __restrict__ Wsig2,
    const float* __restrict__ Wc1, const float* __restrict__ Wc2,
    const float* __restrict__ Wc3, float* __restrict__ outp) {

    __shared__ __align__(16) __half sW1t[64 * WST];
    __shared__ __align__(16) __half sW2t[16 * WST];
    __shared__ __align__(16) __half sC1t[64 * C1ST];
    __shared__ __align__(16) __half sC2t[64 * WST];
    __shared__ float sC3[64 * 3];
    extern __shared__ __align__(16) __half sX[];   // 8 warp tiles

    int tid = threadIdx.x;

    // Weight convert + transpose: W[k][n] f32 -> Wt[n][k] f16.
    for (int idx = tid; idx < 64 * 64; idx += 256) {
        int k = idx >> 6, nn = idx & 63;
        sW1t[nn * WST + k] = __float2half(Wsig1[idx]);
        sC2t[nn * WST + k] = __float2half(Wc2[idx]);
    }
    for (int idx = tid; idx < 64 * 16; idx += 256) {
        int k = idx >> 4, nn = idx & 15;
        sW2t[nn * WST + k] = __float2half(Wsig2[idx]);
    }
    for (int idx = tid; idx < 31 * 64; idx += 256) {
        int k = idx >> 6, nn = idx & 63;
        sC1t[nn * C1ST + k] = __float2half(Wc1[idx]);
    }
    for (int idx = tid; idx < 64; idx += 256) {
        sC1t[idx * C1ST + 31] = __float2half(0.0f);
    }
    for (int idx = tid; idx < 64 * 3; idx += 256) sC3[idx] = Wc3[idx];
    __syncthreads();

    int lane = tid & 31;
    int warp = tid >> 5;
    int n = blockIdx.x * 256 + tid;   // this lane's sample

    __half* Xh = sX + warp * XTILE;
    float*  Xf = (float*)Xh;

    // ================= GATHER PHASE =================
    {
        float p4[4];
        p4[0] = pts[3*n + 0];
        p4[1] = pts[3*n + 1];
        p4[2] = pts[3*n + 2];
        p4[3] = ts[n >> 6] * 2.0f - 1.0f;

        int      oe0, oe1, oe2, oe3, oe4, oe5;
        unsigned a0, a1, a2, a3, a4, a5;
        unsigned b0, b1, b2, b3, b4, b5;
        prep<128,       0, 0, 1>(p4, oe0, a0, b0);
        prep<128, 1048576, 0, 2>(p4, oe1, a1, b1);
        prep<100, 2097152, 0, 3>(p4, oe2, a2, b2);
        prep<128, 2916352, 1, 2>(p4, oe3, a3, b3);
        prep<100, 3964928, 1, 3>(p4, oe4, a4, b4);
        prep<100, 4784128, 2, 3>(p4, oe5, a5, b5);

        int lane2 = 2 * lane;

#pragma unroll 1
        for (int s = 0; s < 32; s++) {
            __half2 prod = __floats2half2_rn(1.0f, 1.0f);

#define DO_COMBO(OE, WA, WB, DYC)                                  \
            {                                                      \
                int      o  = __shfl_sync(0xffffffffu, OE, s);     \
                unsigned u_ = __shfl_sync(0xffffffffu, WA, s);     \
                unsigned v_ = __shfl_sync(0xffffffffu, WB, s);     \
                samp<DYC>(o, u_, v_, lane2, prod);                 \
            }
            DO_COMBO(oe0, a0, b0, 8192)
            DO_COMBO(oe1, a1, b1, 8192)
            DO_COMBO(oe2, a2, b2, 6400)
            DO_COMBO(oe3, a3, b3, 8192)
            DO_COMBO(oe4, a4, b4, 6400)
            DO_COMBO(oe5, a5, b5, 6400)
#undef DO_COMBO

            Xh[s * XS + lane]      = __low2half(prod);
            Xh[s * XS + 32 + lane] = __high2half(prod);
        }
        __syncwarp();
    }

    // ================= MLP PHASE (tensor cores) =================

    // ---- Layer 1: 64 -> 64, relu ----
    mma_layer<4, 8, WST, false>(Xh, sW1t, Xf, lane);

    // ---- Layer 2: 64 -> 16, no relu, fp32 out ----
    mma_layer<4, 2, WST, true>(Xh, sW2t, Xf, lane);

    // ---- Per-lane: density + SH + geo -> ci fp16 ----
    float ov[16];
#pragma unroll
    for (int j = 0; j < 16; j++) ov[j] = Xf[lane * XFS + j];
    float density = expf(fminf(fmaxf(ov[15], -15.0f), 15.0f));

    int r = n >> 6;
    float dxv = dirs[3*r + 0], dyv = dirs[3*r + 1], dzv = dirs[3*r + 2];
    float inv = rsqrtf(dxv*dxv + dyv*dyv + dzv*dzv);
    float X = dxv * inv, Y = dyv * inv, Z = dzv * inv;
    float xx = X * X, yy = Y * Y, zz = Z * Z;

    float ci[32];
    ci[0]  = 0.28209479177387814f;
    ci[1]  = -0.4886025119029199f * Y;
    ci[2]  = 0.4886025119029199f * Z;
    ci[3]  = -0.4886025119029199f * X;
    ci[4]  = 1.0925484305920792f * X * Y;
    ci[5]  = -1.0925484305920792f * Y * Z;
    ci[6]  = 0.31539156525252005f * (3.0f * zz - 1.0f);
    ci[7]  = -1.0925484305920792f * X * Z;
    ci[8]  = 0.5462742152960396f * (xx - yy);
    ci[9]  = -0.5900435899266435f * Y * (3.0f * xx - yy);
    ci[10] = 2.890611442640554f * X * Y * Z;
    ci[11] = -0.4570457994644658f * Y * (5.0f * zz - 1.0f);
    ci[12] = 0.3731763325901154f * Z * (5.0f * zz - 3.0f);
    ci[13] = -0.4570457994644658f * X * (5.0f * zz - 1.0f);
    ci[14] = 1.445305721320277f * Z * (xx - yy);
    ci[15] = -0.5900435899266435f * X * (xx - 3.0f * yy);
#pragma unroll
    for (int g2 = 0; g2 < 15; g2++) ci[16 + g2] = ov[g2];
    ci[31] = 0.0f;

    __syncwarp();   // all lanes done reading Xf before overwriting as fp16
#pragma unroll
    for (int q = 0; q < 16; q++) {
        *(unsigned*)&Xh[lane * XS + 2 * q] = packh2(ci[2*q], ci[2*q + 1]);
    }
    __syncwarp();

    // ---- Layer C1: 32(31+pad) -> 64, relu ----
    mma_layer<2, 8, C1ST, false>(Xh, sC1t, Xf, lane);

    // ---- Layer C2: 64 -> 64, relu ----
    mma_layer<4, 8, WST, false>(Xh, sC2t, Xf, lane);

    // ---- Layer C3 (SIMT): 64 -> 3, sigmoid ----
    float r0 = 0.f, r1 = 0.f, r2 = 0.f;
#pragma unroll
    for (int q = 0; q < 32; q++) {
        float f0, f1;
        unph2(*(const unsigned*)&Xh[lane * XS + 2 * q], f0, f1);
        const float* w0 = sC3 + (2*q) * 3;
        const float* w1 = sC3 + (2*q + 1) * 3;
        r0 += f0 * w0[0] + f1 * w1[0];
        r1 += f0 * w0[1] + f1 * w1[1];
        r2 += f0 * w0[2] + f1 * w1[2];
    }

    float4 res;
    res.x = 1.0f / (1.0f + expf(-r0));
    res.y = 1.0f / (1.0f + expf(-r1));
    res.z = 1.0f / (1.0f + expf(-r2));
    res.w = density;
    *(float4*)(outp + 4 * n) = res;
}

// ---------------------------------------------------------------------------
// Launch
// ---------------------------------------------------------------------------
extern "C" void kernel_launch(void* const* d_in, const int* in_sizes, int n_in,
                              void* d_out, int out_size) {
    const float* pts  = (const float*)d_in[0];
    const float* dirs = (const float*)d_in[1];
    const float* ts   = (const float*)d_in[2];
    const float* yl0 = (const float*)d_in[3];  const float* yh0 = (const float*)d_in[4];
    const float* yl1 = (const float*)d_in[5];  const float* yh1 = (const float*)d_in[6];
    const float* yl2 = (const float*)d_in[7];  const float* yh2 = (const float*)d_in[8];
    const float* yl3 = (const float*)d_in[9];  const float* yh3 = (const float*)d_in[10];
    const float* yl4 = (const float*)d_in[11]; const float* yh4 = (const float*)d_in[12];
    const float* yl5 = (const float*)d_in[13]; const float* yh5 = (const float*)d_in[14];
    const float* Wsig1 = (const float*)d_in[15];
    const float* Wsig2 = (const float*)d_in[16];
    const float* Wc1   = (const float*)d_in[17];
    const float* Wc2   = (const float*)d_in[18];
    const float* Wc3   = (const float*)d_in[19];

    size_t dyn = 8 * XTILE * sizeof(__half);   // 35 KB dynamic X tiles
    // Opt-in: static (~25.8K) + dynamic (35K) > 48K. Host-side immediate
    // call, not a stream op — graph-capture safe (validated in R7).
    cudaFuncSetAttribute(wf_fused, cudaFuncAttributeMaxDynamicSharedMemorySize,
                         (int)dyn);

    idwt_all<<<2736, 256>>>(yl0, yh0, yl1, yh1, yl2, yh2,
                            yl3, yh3, yl4, yh4, yl5, yh5);

    wf_fused<<<NSAMP / 256, 256, dyn>>>(pts, ts, dirs,
                                        Wsig1, Wsig2, Wc1, Wc2, Wc3,
                                        (float*)d_out);
}